// round 5
// baseline (speedup 1.0000x reference)
#include <cuda_runtime.h>
#include <math.h>

#define T_SEQ 2048
#define D_MOD 256
#define N_BH  32
#define M_TOT (N_BH * T_SEQ)   /* 65536 */
#define EPS_F 1e-8f

// ---- scratch (device globals; no runtime allocation allowed) ----
__device__ float g_qr[M_TOT * D_MOD];
__device__ float g_qi[M_TOT * D_MOD];
__device__ float g_kr[M_TOT * D_MOD];
__device__ float g_ki[M_TOT * D_MOD];
__device__ float g_vr[M_TOT * D_MOD];
__device__ float g_vi[M_TOT * D_MOD];
__device__ float g_cr[M_TOT * D_MOD];
__device__ float g_ci[M_TOT * D_MOD];
__device__ float g_outr[M_TOT * D_MOD];
__device__ float g_outi[M_TOT * D_MOD];
__device__ float g_gate[M_TOT * D_MOD];
__device__ float g_sc[(size_t)N_BH * T_SEQ * T_SEQ];   /* 512 MB */

// ============================================================================
// Complex GEMM NT:  Cr = Ar*Wr^T - Ai*Wi^T + bR ; Ci = Ai*Wr^T + Ar*Wi^T + bI
// A: [M_TOT, 256], W: [256, 256] row-major.  BM=128, BN=64, BK=8, 256 thr.
// ============================================================================
__global__ __launch_bounds__(256) void cgemm_nt(
    const float* __restrict__ Ar, const float* __restrict__ Ai,
    const float* __restrict__ Wr, const float* __restrict__ Wi,
    const float* __restrict__ bR, const float* __restrict__ bI,
    float* __restrict__ Cr, float* __restrict__ Ci)
{
    __shared__ float Asr[8][132], Asi[8][132], Bsr[8][68], Bsi[8][68];
    const int tid = threadIdx.x;
    const int bm = blockIdx.x * 128;
    const int bn = blockIdx.y * 64;
    const int ty = tid >> 4, tx = tid & 15;
    const int lrow = tid >> 1;
    const int lk   = (tid & 1) << 2;
    const int brow = (tid & 127) >> 1;
    const float* Wsel = (tid < 128) ? Wr : Wi;
    float* bdst = (tid < 128) ? &Bsr[0][0] : &Bsi[0][0];

    float cr[8][4], ci[8][4];
#pragma unroll
    for (int i = 0; i < 8; i++)
#pragma unroll
        for (int j = 0; j < 4; j++) { cr[i][j] = 0.f; ci[i][j] = 0.f; }

    for (int k0 = 0; k0 < 256; k0 += 8) {
        float4 a0 = *(const float4*)(Ar + (size_t)(bm + lrow) * 256 + k0 + lk);
        float4 a1 = *(const float4*)(Ai + (size_t)(bm + lrow) * 256 + k0 + lk);
        float4 w  = *(const float4*)(Wsel + (size_t)(bn + brow) * 256 + k0 + lk);
        Asr[lk+0][lrow] = a0.x; Asr[lk+1][lrow] = a0.y;
        Asr[lk+2][lrow] = a0.z; Asr[lk+3][lrow] = a0.w;
        Asi[lk+0][lrow] = a1.x; Asi[lk+1][lrow] = a1.y;
        Asi[lk+2][lrow] = a1.z; Asi[lk+3][lrow] = a1.w;
        bdst[(lk+0)*68 + brow] = w.x; bdst[(lk+1)*68 + brow] = w.y;
        bdst[(lk+2)*68 + brow] = w.z; bdst[(lk+3)*68 + brow] = w.w;
        __syncthreads();
#pragma unroll
        for (int kk = 0; kk < 8; kk++) {
            float4 r0 = *(const float4*)&Asr[kk][ty*8];
            float4 r1 = *(const float4*)&Asr[kk][ty*8+4];
            float4 i0 = *(const float4*)&Asi[kk][ty*8];
            float4 i1 = *(const float4*)&Asi[kk][ty*8+4];
            float4 wr4 = *(const float4*)&Bsr[kk][tx*4];
            float4 wi4 = *(const float4*)&Bsi[kk][tx*4];
            float ar[8] = {r0.x,r0.y,r0.z,r0.w,r1.x,r1.y,r1.z,r1.w};
            float ai[8] = {i0.x,i0.y,i0.z,i0.w,i1.x,i1.y,i1.z,i1.w};
            float br[4] = {wr4.x,wr4.y,wr4.z,wr4.w};
            float bi[4] = {wi4.x,wi4.y,wi4.z,wi4.w};
#pragma unroll
            for (int i = 0; i < 8; i++)
#pragma unroll
                for (int j = 0; j < 4; j++) {
                    cr[i][j] = fmaf(ar[i], br[j], cr[i][j]);
                    cr[i][j] = fmaf(-ai[i], bi[j], cr[i][j]);
                    ci[i][j] = fmaf(ai[i], br[j], ci[i][j]);
                    ci[i][j] = fmaf(ar[i], bi[j], ci[i][j]);
                }
        }
        __syncthreads();
    }
    float4 br4 = *(const float4*)(bR + bn + tx*4);
    float4 bi4 = *(const float4*)(bI + bn + tx*4);
#pragma unroll
    for (int i = 0; i < 8; i++) {
        const size_t row = (size_t)(bm + ty*8 + i);
        float4 o, p;
        o.x = cr[i][0] + br4.x; o.y = cr[i][1] + br4.y;
        o.z = cr[i][2] + br4.z; o.w = cr[i][3] + br4.w;
        p.x = ci[i][0] + bi4.x; p.y = ci[i][1] + bi4.y;
        p.z = ci[i][2] + bi4.z; p.w = ci[i][3] + bi4.w;
        *(float4*)(Cr + row*256 + bn + tx*4) = o;
        *(float4*)(Ci + row*256 + bn + tx*4) = p;
    }
}

// ============================================================================
// Scores: S[bh] = (Qr Kr^T + Qi Ki^T) * scale.  BM=BN=128, BK=8, 8x8 microtile.
// ============================================================================
__global__ __launch_bounds__(256) void score_gemm(
    const float* __restrict__ Qr, const float* __restrict__ Qi,
    const float* __restrict__ Kr, const float* __restrict__ Ki,
    float* __restrict__ S, float scale)
{
    __shared__ float Qsr[8][132], Qsi[8][132], Ksr[8][132], Ksi[8][132];
    const int bh = blockIdx.z;
    const size_t off = (size_t)bh * T_SEQ * D_MOD;
    const float* qr = Qr + off; const float* qi = Qi + off;
    const float* kr = Kr + off; const float* ki = Ki + off;
    float* s = S + (size_t)bh * T_SEQ * T_SEQ;
    const int bm = blockIdx.x * 128, bn = blockIdx.y * 128;
    const int tid = threadIdx.x;
    const int ty = tid >> 4, tx = tid & 15;
    const int lrow = tid >> 1;
    const int lk   = (tid & 1) << 2;

    float acc[8][8];
#pragma unroll
    for (int i = 0; i < 8; i++)
#pragma unroll
        for (int j = 0; j < 8; j++) acc[i][j] = 0.f;

    for (int k0 = 0; k0 < 256; k0 += 8) {
        float4 a0 = *(const float4*)(qr + (size_t)(bm + lrow) * 256 + k0 + lk);
        float4 a1 = *(const float4*)(qi + (size_t)(bm + lrow) * 256 + k0 + lk);
        float4 b0 = *(const float4*)(kr + (size_t)(bn + lrow) * 256 + k0 + lk);
        float4 b1 = *(const float4*)(ki + (size_t)(bn + lrow) * 256 + k0 + lk);
        Qsr[lk+0][lrow] = a0.x; Qsr[lk+1][lrow] = a0.y;
        Qsr[lk+2][lrow] = a0.z; Qsr[lk+3][lrow] = a0.w;
        Qsi[lk+0][lrow] = a1.x; Qsi[lk+1][lrow] = a1.y;
        Qsi[lk+2][lrow] = a1.z; Qsi[lk+3][lrow] = a1.w;
        Ksr[lk+0][lrow] = b0.x; Ksr[lk+1][lrow] = b0.y;
        Ksr[lk+2][lrow] = b0.z; Ksr[lk+3][lrow] = b0.w;
        Ksi[lk+0][lrow] = b1.x; Ksi[lk+1][lrow] = b1.y;
        Ksi[lk+2][lrow] = b1.z; Ksi[lk+3][lrow] = b1.w;
        __syncthreads();
#pragma unroll
        for (int kk = 0; kk < 8; kk++) {
            float4 q0 = *(const float4*)&Qsr[kk][ty*8];
            float4 q1 = *(const float4*)&Qsr[kk][ty*8+4];
            float4 u0 = *(const float4*)&Qsi[kk][ty*8];
            float4 u1 = *(const float4*)&Qsi[kk][ty*8+4];
            float4 c0 = *(const float4*)&Ksr[kk][tx*8];
            float4 c1 = *(const float4*)&Ksr[kk][tx*8+4];
            float4 d0 = *(const float4*)&Ksi[kk][tx*8];
            float4 d1 = *(const float4*)&Ksi[kk][tx*8+4];
            float qrv[8] = {q0.x,q0.y,q0.z,q0.w,q1.x,q1.y,q1.z,q1.w};
            float qiv[8] = {u0.x,u0.y,u0.z,u0.w,u1.x,u1.y,u1.z,u1.w};
            float krv[8] = {c0.x,c0.y,c0.z,c0.w,c1.x,c1.y,c1.z,c1.w};
            float kiv[8] = {d0.x,d0.y,d0.z,d0.w,d1.x,d1.y,d1.z,d1.w};
#pragma unroll
            for (int i = 0; i < 8; i++)
#pragma unroll
                for (int j = 0; j < 8; j++) {
                    acc[i][j] = fmaf(qrv[i], krv[j], acc[i][j]);
                    acc[i][j] = fmaf(qiv[i], kiv[j], acc[i][j]);
                }
        }
        __syncthreads();
    }
#pragma unroll
    for (int i = 0; i < 8; i++) {
        const size_t row = (size_t)(bm + ty*8 + i);
        float4 o0, o1;
        o0.x = acc[i][0]*scale; o0.y = acc[i][1]*scale;
        o0.z = acc[i][2]*scale; o0.w = acc[i][3]*scale;
        o1.x = acc[i][4]*scale; o1.y = acc[i][5]*scale;
        o1.z = acc[i][6]*scale; o1.w = acc[i][7]*scale;
        *(float4*)(s + row*T_SEQ + bn + tx*8)     = o0;
        *(float4*)(s + row*T_SEQ + bn + tx*8 + 4) = o1;
    }
}

// ============================================================================
// Row softmax over T_SEQ=2048, one block per row, values held in registers.
// ============================================================================
__global__ __launch_bounds__(256) void softmax_rows(float* __restrict__ S)
{
    float* p = S + (size_t)blockIdx.x * T_SEQ;
    const int tid = threadIdx.x;
    float v[8];
    float m = -3.4e38f;
#pragma unroll
    for (int r = 0; r < 8; r++) { v[r] = p[tid + (r << 8)]; m = fmaxf(m, v[r]); }
#pragma unroll
    for (int o = 16; o > 0; o >>= 1) m = fmaxf(m, __shfl_xor_sync(0xffffffffu, m, o));
    __shared__ float red[8];
    if ((tid & 31) == 0) red[tid >> 5] = m;
    __syncthreads();
    m = red[0];
#pragma unroll
    for (int w = 1; w < 8; w++) m = fmaxf(m, red[w]);
    float sum = 0.f;
#pragma unroll
    for (int r = 0; r < 8; r++) { v[r] = __expf(v[r] - m); sum += v[r]; }
#pragma unroll
    for (int o = 16; o > 0; o >>= 1) sum += __shfl_xor_sync(0xffffffffu, sum, o);
    __syncthreads();
    if ((tid & 31) == 0) red[tid >> 5] = sum;
    __syncthreads();
    sum = 0.f;
#pragma unroll
    for (int w = 0; w < 8; w++) sum += red[w];
    const float inv = 1.f / sum;
#pragma unroll
    for (int r = 0; r < 8; r++) p[tid + (r << 8)] = v[r] * inv;
}

// ============================================================================
// Context: Cr[bh] = attn @ Vr, Ci[bh] = attn @ Vi (NN, shared A tile).
// BM=128, BN=64, BK=8.
// ============================================================================
__global__ __launch_bounds__(256) void ctx_gemm(
    const float* __restrict__ S, const float* __restrict__ Vr,
    const float* __restrict__ Vi,
    float* __restrict__ Cr, float* __restrict__ Ci)
{
    __shared__ float As[8][132], Bsr[8][68], Bsi[8][68];
    const int bh = blockIdx.z;
    const float* a  = S  + (size_t)bh * T_SEQ * T_SEQ;
    const float* vr = Vr + (size_t)bh * T_SEQ * D_MOD;
    const float* vi = Vi + (size_t)bh * T_SEQ * D_MOD;
    float* crp = Cr + (size_t)bh * T_SEQ * D_MOD;
    float* cip = Ci + (size_t)bh * T_SEQ * D_MOD;
    const int bm = blockIdx.x * 128, bn = blockIdx.y * 64;
    const int tid = threadIdx.x;
    const int ty = tid >> 4, tx = tid & 15;
    const int lrow = tid >> 1;
    const int lk   = (tid & 1) << 2;
    const int bmat = tid >> 7;          // 0 -> Vr, 1 -> Vi
    const int bkr  = (tid >> 4) & 7;    // k row within tile
    const int bnc  = (tid & 15) << 2;   // n col within tile
    const float* vsel = bmat ? vi : vr;
    float* bdst = bmat ? &Bsi[0][0] : &Bsr[0][0];

    float cr[8][4], ci[8][4];
#pragma unroll
    for (int i = 0; i < 8; i++)
#pragma unroll
        for (int j = 0; j < 4; j++) { cr[i][j] = 0.f; ci[i][j] = 0.f; }

    for (int k0 = 0; k0 < T_SEQ; k0 += 8) {
        float4 a4 = *(const float4*)(a + (size_t)(bm + lrow) * T_SEQ + k0 + lk);
        As[lk+0][lrow] = a4.x; As[lk+1][lrow] = a4.y;
        As[lk+2][lrow] = a4.z; As[lk+3][lrow] = a4.w;
        float4 v4 = *(const float4*)(vsel + (size_t)(k0 + bkr) * 256 + bn + bnc);
        *(float4*)&bdst[bkr*68 + bnc] = v4;
        __syncthreads();
#pragma unroll
        for (int kk = 0; kk < 8; kk++) {
            float4 a0 = *(const float4*)&As[kk][ty*8];
            float4 a1 = *(const float4*)&As[kk][ty*8+4];
            float4 br4 = *(const float4*)&Bsr[kk][tx*4];
            float4 bi4 = *(const float4*)&Bsi[kk][tx*4];
            float av[8] = {a0.x,a0.y,a0.z,a0.w,a1.x,a1.y,a1.z,a1.w};
            float br[4] = {br4.x,br4.y,br4.z,br4.w};
            float bi[4] = {bi4.x,bi4.y,bi4.z,bi4.w};
#pragma unroll
            for (int i = 0; i < 8; i++)
#pragma unroll
                for (int j = 0; j < 4; j++) {
                    cr[i][j] = fmaf(av[i], br[j], cr[i][j]);
                    ci[i][j] = fmaf(av[i], bi[j], ci[i][j]);
                }
        }
        __syncthreads();
    }
#pragma unroll
    for (int i = 0; i < 8; i++) {
        const size_t row = (size_t)(bm + ty*8 + i);
        float4 o = {cr[i][0], cr[i][1], cr[i][2], cr[i][3]};
        float4 p = {ci[i][0], ci[i][1], ci[i][2], ci[i][3]};
        *(float4*)(crp + row*256 + bn + tx*4) = o;
        *(float4*)(cip + row*256 + bn + tx*4) = p;
    }
}

// ============================================================================
// Gate GEMM: G = sigmoid( mag(Or,Oi) @ W^T + bias ), mag computed on A-load.
// BM=128, BN=64, BK=8.
// ============================================================================
__global__ __launch_bounds__(256) void gate_gemm(
    const float* __restrict__ Or, const float* __restrict__ Oi,
    const float* __restrict__ W, const float* __restrict__ bias,
    float* __restrict__ G)
{
    __shared__ float As[8][132], Bs[8][68];
    const int bm = blockIdx.x * 128, bn = blockIdx.y * 64;
    const int tid = threadIdx.x;
    const int ty = tid >> 4, tx = tid & 15;
    const int lrow = tid >> 1;
    const int lk   = (tid & 1) << 2;
    const int brow = (tid & 127) >> 1;

    float c[8][4];
#pragma unroll
    for (int i = 0; i < 8; i++)
#pragma unroll
        for (int j = 0; j < 4; j++) c[i][j] = 0.f;

    for (int k0 = 0; k0 < 256; k0 += 8) {
        float4 o1 = *(const float4*)(Or + (size_t)(bm + lrow) * 256 + k0 + lk);
        float4 o2 = *(const float4*)(Oi + (size_t)(bm + lrow) * 256 + k0 + lk);
        As[lk+0][lrow] = sqrtf(o1.x*o1.x + o2.x*o2.x + EPS_F);
        As[lk+1][lrow] = sqrtf(o1.y*o1.y + o2.y*o2.y + EPS_F);
        As[lk+2][lrow] = sqrtf(o1.z*o1.z + o2.z*o2.z + EPS_F);
        As[lk+3][lrow] = sqrtf(o1.w*o1.w + o2.w*o2.w + EPS_F);
        if (tid < 128) {
            float4 w = *(const float4*)(W + (size_t)(bn + brow) * 256 + k0 + lk);
            Bs[lk+0][brow] = w.x; Bs[lk+1][brow] = w.y;
            Bs[lk+2][brow] = w.z; Bs[lk+3][brow] = w.w;
        }
        __syncthreads();
#pragma unroll
        for (int kk = 0; kk < 8; kk++) {
            float4 a0 = *(const float4*)&As[kk][ty*8];
            float4 a1 = *(const float4*)&As[kk][ty*8+4];
            float4 b4 = *(const float4*)&Bs[kk][tx*4];
            float av[8] = {a0.x,a0.y,a0.z,a0.w,a1.x,a1.y,a1.z,a1.w};
            float bv[4] = {b4.x,b4.y,b4.z,b4.w};
#pragma unroll
            for (int i = 0; i < 8; i++)
#pragma unroll
                for (int j = 0; j < 4; j++)
                    c[i][j] = fmaf(av[i], bv[j], c[i][j]);
        }
        __syncthreads();
    }
    float4 b4 = *(const float4*)(bias + bn + tx*4);
#pragma unroll
    for (int i = 0; i < 8; i++) {
        const size_t row = (size_t)(bm + ty*8 + i);
        float4 g;
        g.x = 1.f / (1.f + __expf(-(c[i][0] + b4.x)));
        g.y = 1.f / (1.f + __expf(-(c[i][1] + b4.y)));
        g.z = 1.f / (1.f + __expf(-(c[i][2] + b4.z)));
        g.w = 1.f / (1.f + __expf(-(c[i][3] + b4.w)));
        *(float4*)(G + row*256 + bn + tx*4) = g;
    }
}

// ============================================================================
// Finalize: out[0:N) = Or*G, out[N:2N) = Oi*G
// ============================================================================
__global__ __launch_bounds__(256) void finalize_kernel(
    const float* __restrict__ Or, const float* __restrict__ Oi,
    const float* __restrict__ G, float* __restrict__ out)
{
    const size_t i = ((size_t)blockIdx.x * 256 + threadIdx.x) * 4;
    float4 a = *(const float4*)(Or + i);
    float4 b = *(const float4*)(Oi + i);
    float4 g = *(const float4*)(G + i);
    float4 x, y;
    x.x = a.x*g.x; x.y = a.y*g.y; x.z = a.z*g.z; x.w = a.w*g.w;
    y.x = b.x*g.x; y.y = b.y*g.y; y.z = b.z*g.z; y.w = b.w*g.w;
    *(float4*)(out + i) = x;
    *(float4*)(out + (size_t)M_TOT * D_MOD + i) = y;
}

// ============================================================================
extern "C" void kernel_launch(void* const* d_in, const int* in_sizes, int n_in,
                              void* d_out, int out_size)
{
    const float* q_in_r  = (const float*)d_in[0];
    const float* q_in_i  = (const float*)d_in[1];
    const float* kv_in_r = (const float*)d_in[2];
    const float* kv_in_i = (const float*)d_in[3];
    const float* q_wr = (const float*)d_in[4];
    const float* q_wi = (const float*)d_in[5];
    const float* q_br = (const float*)d_in[6];
    const float* q_bi = (const float*)d_in[7];
    const float* k_wr = (const float*)d_in[8];
    const float* k_wi = (const float*)d_in[9];
    const float* k_br = (const float*)d_in[10];
    const float* k_bi = (const float*)d_in[11];
    const float* v_wr = (const float*)d_in[12];
    const float* v_wi = (const float*)d_in[13];
    const float* v_br = (const float*)d_in[14];
    const float* v_bi = (const float*)d_in[15];
    const float* o_wr = (const float*)d_in[16];
    const float* o_wi = (const float*)d_in[17];
    const float* o_br = (const float*)d_in[18];
    const float* o_bi = (const float*)d_in[19];
    const float* gate_w = (const float*)d_in[20];
    const float* gate_b = (const float*)d_in[21];

    float *p_qr, *p_qi, *p_kr, *p_ki, *p_vr, *p_vi;
    float *p_cr, *p_ci, *p_or, *p_oi, *p_g, *p_sc;
    cudaGetSymbolAddress((void**)&p_qr, g_qr);
    cudaGetSymbolAddress((void**)&p_qi, g_qi);
    cudaGetSymbolAddress((void**)&p_kr, g_kr);
    cudaGetSymbolAddress((void**)&p_ki, g_ki);
    cudaGetSymbolAddress((void**)&p_vr, g_vr);
    cudaGetSymbolAddress((void**)&p_vi, g_vi);
    cudaGetSymbolAddress((void**)&p_cr, g_cr);
    cudaGetSymbolAddress((void**)&p_ci, g_ci);
    cudaGetSymbolAddress((void**)&p_or, g_outr);
    cudaGetSymbolAddress((void**)&p_oi, g_outi);
    cudaGetSymbolAddress((void**)&p_g,  g_gate);
    cudaGetSymbolAddress((void**)&p_sc, g_sc);

    const dim3 tpb(256);
    const dim3 proj_grid(M_TOT / 128, D_MOD / 64);

    // Projections
    cgemm_nt<<<proj_grid, tpb>>>(q_in_r, q_in_i, q_wr, q_wi, q_br, q_bi, p_qr, p_qi);
    cgemm_nt<<<proj_grid, tpb>>>(kv_in_r, kv_in_i, k_wr, k_wi, k_br, k_bi, p_kr, p_ki);
    cgemm_nt<<<proj_grid, tpb>>>(kv_in_r, kv_in_i, v_wr, v_wi, v_br, v_bi, p_vr, p_vi);

    // Attention
    score_gemm<<<dim3(T_SEQ/128, T_SEQ/128, N_BH), tpb>>>(p_qr, p_qi, p_kr, p_ki,
                                                          p_sc, 0.0625f);
    softmax_rows<<<(unsigned)(N_BH * T_SEQ), tpb>>>(p_sc);
    ctx_gemm<<<dim3(T_SEQ/128, D_MOD/64, N_BH), tpb>>>(p_sc, p_vr, p_vi, p_cr, p_ci);

    // Output projection + gating
    cgemm_nt<<<proj_grid, tpb>>>(p_cr, p_ci, o_wr, o_wi, o_br, o_bi, p_or, p_oi);
    gate_gemm<<<proj_grid, tpb>>>(p_or, p_oi, gate_w, gate_b, p_g);
    finalize_kernel<<<(M_TOT * D_MOD) / (256 * 4), tpb>>>(p_or, p_oi, p_g, (float*)d_out);
}

// round 11
// speedup vs baseline: 1.7052x; 1.7052x over previous
#include <cuda_runtime.h>
#include <cuda_bf16.h>
#include <cuda_fp16.h>
#include <math.h>
#include <stdint.h>

#define T_SEQ 2048
#define D_MOD 256
#define N_BH  32
#define M_TOT (N_BH * T_SEQ)   /* 65536 */
#define EPS_F 1e-8f
#define KCAT  1536              /* split-bf16 concatenated K for scores */

// ---- scratch (device globals; no runtime allocation allowed) ----
__device__ float g_qr[M_TOT * D_MOD];
__device__ float g_qi[M_TOT * D_MOD];
__device__ float g_kr[M_TOT * D_MOD];
__device__ float g_ki[M_TOT * D_MOD];
__device__ float g_vr[M_TOT * D_MOD];
__device__ float g_vi[M_TOT * D_MOD];
__device__ float g_cr[M_TOT * D_MOD];
__device__ float g_ci[M_TOT * D_MOD];
__device__ float g_outr[M_TOT * D_MOD];
__device__ float g_outi[M_TOT * D_MOD];
__device__ float g_gate[M_TOT * D_MOD];
__device__ float g_sc[(size_t)N_BH * T_SEQ * T_SEQ];          /* 512 MB fp32 scores */
__device__ __half g_attn[(size_t)N_BH * T_SEQ * T_SEQ];       /* 256 MB fp16 attn  */
__device__ __nv_bfloat16 g_qcat[(size_t)M_TOT * KCAT];        /* 192 MB split-bf16 */
__device__ __nv_bfloat16 g_kcat[(size_t)M_TOT * KCAT];        /* 192 MB split-bf16 */
__device__ __half g_vtr[(size_t)N_BH * D_MOD * T_SEQ];        /* 32 MB V^T fp16    */
__device__ __half g_vti[(size_t)N_BH * D_MOD * T_SEQ];        /* 32 MB V^T fp16    */

// ============================================================================
// helpers
// ============================================================================
__device__ __forceinline__ uint32_t smem_to_u32(const void* smem_ptr) {
    uint32_t addr;
    asm("{ .reg .u64 tmp; cvta.to.shared.u64 tmp, %1; cvt.u32.u64 %0, tmp; }"
        : "=r"(addr) : "l"(smem_ptr));
    return addr;
}
__device__ __forceinline__ void cp16(uint32_t smem_addr, const void* gptr) {
    asm volatile("cp.async.cg.shared.global [%0], [%1], 16;"
                 :: "r"(smem_addr), "l"(gptr) : "memory");
}
__device__ __forceinline__ void ldsm_x4(uint32_t* r, uint32_t addr) {
    asm volatile("ldmatrix.sync.aligned.m8n8.x4.shared.b16 {%0,%1,%2,%3}, [%4];"
                 : "=r"(r[0]), "=r"(r[1]), "=r"(r[2]), "=r"(r[3]) : "r"(addr));
}
__device__ __forceinline__ void ldsm_x2(uint32_t* r, uint32_t addr) {
    asm volatile("ldmatrix.sync.aligned.m8n8.x2.shared.b16 {%0,%1}, [%2];"
                 : "=r"(r[0]), "=r"(r[1]) : "r"(addr));
}
__device__ __forceinline__ void mma_bf16(float* d, const uint32_t* a, const uint32_t* b) {
    asm volatile(
        "mma.sync.aligned.m16n8k16.row.col.f32.bf16.bf16.f32 "
        "{%0,%1,%2,%3}, {%4,%5,%6,%7}, {%8,%9}, {%0,%1,%2,%3};"
        : "+f"(d[0]), "+f"(d[1]), "+f"(d[2]), "+f"(d[3])
        : "r"(a[0]), "r"(a[1]), "r"(a[2]), "r"(a[3]), "r"(b[0]), "r"(b[1]));
}
__device__ __forceinline__ void mma_f16(float* d, const uint32_t* a, const uint32_t* b) {
    asm volatile(
        "mma.sync.aligned.m16n8k16.row.col.f32.f16.f16.f32 "
        "{%0,%1,%2,%3}, {%4,%5,%6,%7}, {%8,%9}, {%0,%1,%2,%3};"
        : "+f"(d[0]), "+f"(d[1]), "+f"(d[2]), "+f"(d[3])
        : "r"(a[0]), "r"(a[1]), "r"(a[2]), "r"(a[3]), "r"(b[0]), "r"(b[1]));
}

// ============================================================================
// Generic 128x128 NT tile GEMM on mma.sync (A,B K-major 16-bit), fp32 out.
// 256 threads = 8 warps in 2(m) x 4(n); warp tile 64x32; Kblk=32, cp.async
// double-buffered.
// ============================================================================
template<bool BF16, int KTOT>
__device__ __forceinline__ void gemm_mma_body(
    const uint16_t* __restrict__ Ag, const uint16_t* __restrict__ Bg,
    float* __restrict__ Cg, int ldc, float scale)
{
    __shared__ uint16_t As[2][128][40];
    __shared__ uint16_t Bs[2][128][40];
    const int tid = threadIdx.x;
    const int wid = tid >> 5, lane = tid & 31;
    const int wm = wid & 1, wn = wid >> 1;

    float acc[4][4][4];
#pragma unroll
    for (int i = 0; i < 4; i++)
#pragma unroll
        for (int j = 0; j < 4; j++)
#pragma unroll
            for (int v = 0; v < 4; v++) acc[i][j][v] = 0.f;

    const uint32_t as0 = smem_to_u32(&As[0][0][0]);
    const uint32_t bs0 = smem_to_u32(&Bs[0][0][0]);
    const int c0 = tid, c1 = tid + 256;
    const int r0 = c0 >> 2, o0 = (c0 & 3) * 8;
    const int r1 = c1 >> 2, o1 = (c1 & 3) * 8;
    const uint32_t s0 = (uint32_t)((r0 * 40 + o0) * 2);
    const uint32_t s1 = (uint32_t)((r1 * 40 + o1) * 2);

    constexpr int NIT = KTOT / 32;
    // prologue
    {
        cp16(as0 + s0, Ag + (size_t)r0 * KTOT + o0);
        cp16(bs0 + s0, Bg + (size_t)r0 * KTOT + o0);
        cp16(as0 + s1, Ag + (size_t)r1 * KTOT + o1);
        cp16(bs0 + s1, Bg + (size_t)r1 * KTOT + o1);
        asm volatile("cp.async.commit_group;" ::: "memory");
    }
    for (int it = 0; it < NIT; it++) {
        if (it + 1 < NIT) {
            const int k0 = (it + 1) * 32;
            const uint32_t bo = (uint32_t)(((it + 1) & 1) * 10240);
            cp16(as0 + bo + s0, Ag + (size_t)r0 * KTOT + k0 + o0);
            cp16(bs0 + bo + s0, Bg + (size_t)r0 * KTOT + k0 + o0);
            cp16(as0 + bo + s1, Ag + (size_t)r1 * KTOT + k0 + o1);
            cp16(bs0 + bo + s1, Bg + (size_t)r1 * KTOT + k0 + o1);
            asm volatile("cp.async.commit_group;" ::: "memory");
            asm volatile("cp.async.wait_group 1;" ::: "memory");
        } else {
            asm volatile("cp.async.wait_group 0;" ::: "memory");
        }
        __syncthreads();
        const uint32_t ab = as0 + (uint32_t)((it & 1) * 10240);
        const uint32_t bb = bs0 + (uint32_t)((it & 1) * 10240);
#pragma unroll
        for (int ks = 0; ks < 32; ks += 16) {
            uint32_t af[4][4], bf[4][2];
            const int ar = lane & 15, ac = ks + ((lane >> 4) << 3);
#pragma unroll
            for (int i = 0; i < 4; i++)
                ldsm_x4(af[i], ab + (uint32_t)(((wm * 64 + i * 16 + ar) * 40 + ac) << 1));
            const int l = lane & 15;
            const int br_ = l & 7, bc = ks + ((l >> 3) << 3);
#pragma unroll
            for (int j = 0; j < 4; j++)
                ldsm_x2(bf[j], bb + (uint32_t)(((wn * 32 + j * 8 + br_) * 40 + bc) << 1));
#pragma unroll
            for (int i = 0; i < 4; i++)
#pragma unroll
                for (int j = 0; j < 4; j++) {
                    if (BF16) mma_bf16(acc[i][j], af[i], bf[j]);
                    else      mma_f16(acc[i][j], af[i], bf[j]);
                }
        }
        __syncthreads();
    }
#pragma unroll
    for (int i = 0; i < 4; i++) {
        const int row = wm * 64 + i * 16 + (lane >> 2);
#pragma unroll
        for (int j = 0; j < 4; j++) {
            const int col = wn * 32 + j * 8 + (lane & 3) * 2;
            float2 v0 = make_float2(acc[i][j][0] * scale, acc[i][j][1] * scale);
            float2 v1 = make_float2(acc[i][j][2] * scale, acc[i][j][3] * scale);
            *(float2*)(Cg + (size_t)row * ldc + col) = v0;
            *(float2*)(Cg + (size_t)(row + 8) * ldc + col) = v1;
        }
    }
}

// Scores: S = Qcat @ Kcat^T * scale, K=1536 split-bf16 (exact cross terms)
__global__ __launch_bounds__(256) void score_mma(
    const __nv_bfloat16* __restrict__ Q, const __nv_bfloat16* __restrict__ K,
    float* __restrict__ S)
{
    const int head = blockIdx.z;
    const int bm = blockIdx.x * 128, bn = blockIdx.y * 128;
    const uint16_t* A = (const uint16_t*)(Q + ((size_t)head * T_SEQ + bm) * KCAT);
    const uint16_t* B = (const uint16_t*)(K + ((size_t)head * T_SEQ + bn) * KCAT);
    float* C = S + ((size_t)head * T_SEQ + bm) * T_SEQ + bn;
    gemm_mma_body<true, KCAT>(A, B, C, T_SEQ, 0.0625f);
}

// Context: C[r|i] = attn @ Vt^T, fp16, K=2048. grid (16, 2, 64) z=head*2+part
__global__ __launch_bounds__(256) void ctx_mma(
    const __half* __restrict__ Attn, const __half* __restrict__ Vtr,
    const __half* __restrict__ Vti,
    float* __restrict__ Cr, float* __restrict__ Ci)
{
    const int bz = blockIdx.z;
    const int head = bz >> 1, part = bz & 1;
    const int bm = blockIdx.x * 128, bn = blockIdx.y * 128;
    const uint16_t* A = (const uint16_t*)(Attn + ((size_t)head * T_SEQ + bm) * T_SEQ);
    const __half* Vt = part ? Vti : Vtr;
    const uint16_t* B = (const uint16_t*)(Vt + ((size_t)head * D_MOD + bn) * T_SEQ);
    float* Cbase = part ? Ci : Cr;
    float* C = Cbase + ((size_t)head * T_SEQ + bm) * D_MOD + bn;
    gemm_mma_body<false, T_SEQ>(A, B, C, D_MOD, 1.0f);
}

// ============================================================================
// Complex GEMM NT (fp32 SIMT — projections):
// Cr = Ar*Wr^T - Ai*Wi^T + bR ; Ci = Ai*Wr^T + Ar*Wi^T + bI
// ============================================================================
__global__ __launch_bounds__(256) void cgemm_nt(
    const float* __restrict__ Ar, const float* __restrict__ Ai,
    const float* __restrict__ Wr, const float* __restrict__ Wi,
    const float* __restrict__ bR, const float* __restrict__ bI,
    float* __restrict__ Cr, float* __restrict__ Ci)
{
    __shared__ float Asr[8][132], Asi[8][132], Bsr[8][68], Bsi[8][68];
    const int tid = threadIdx.x;
    const int bm = blockIdx.x * 128;
    const int bn = blockIdx.y * 64;
    const int ty = tid >> 4, tx = tid & 15;
    const int lrow = tid >> 1;
    const int lk   = (tid & 1) << 2;
    const int brow = (tid & 127) >> 1;
    const float* Wsel = (tid < 128) ? Wr : Wi;
    float* bdst = (tid < 128) ? &Bsr[0][0] : &Bsi[0][0];

    float cr[8][4], ci[8][4];
#pragma unroll
    for (int i = 0; i < 8; i++)
#pragma unroll
        for (int j = 0; j < 4; j++) { cr[i][j] = 0.f; ci[i][j] = 0.f; }

    for (int k0 = 0; k0 < 256; k0 += 8) {
        float4 a0 = *(const float4*)(Ar + (size_t)(bm + lrow) * 256 + k0 + lk);
        float4 a1 = *(const float4*)(Ai + (size_t)(bm + lrow) * 256 + k0 + lk);
        float4 w  = *(const float4*)(Wsel + (size_t)(bn + brow) * 256 + k0 + lk);
        Asr[lk+0][lrow] = a0.x; Asr[lk+1][lrow] = a0.y;
        Asr[lk+2][lrow] = a0.z; Asr[lk+3][lrow] = a0.w;
        Asi[lk+0][lrow] = a1.x; Asi[lk+1][lrow] = a1.y;
        Asi[lk+2][lrow] = a1.z; Asi[lk+3][lrow] = a1.w;
        bdst[(lk+0)*68 + brow] = w.x; bdst[(lk+1)*68 + brow] = w.y;
        bdst[(lk+2)*68 + brow] = w.z; bdst[(lk+3)*68 + brow] = w.w;
        __syncthreads();
#pragma unroll
        for (int kk = 0; kk < 8; kk++) {
            float4 r0 = *(const float4*)&Asr[kk][ty*8];
            float4 r1 = *(const float4*)&Asr[kk][ty*8+4];
            float4 i0 = *(const float4*)&Asi[kk][ty*8];
            float4 i1 = *(const float4*)&Asi[kk][ty*8+4];
            float4 wr4 = *(const float4*)&Bsr[kk][tx*4];
            float4 wi4 = *(const float4*)&Bsi[kk][tx*4];
            float ar[8] = {r0.x,r0.y,r0.z,r0.w,r1.x,r1.y,r1.z,r1.w};
            float ai[8] = {i0.x,i0.y,i0.z,i0.w,i1.x,i1.y,i1.z,i1.w};
            float br[4] = {wr4.x,wr4.y,wr4.z,wr4.w};
            float bi[4] = {wi4.x,wi4.y,wi4.z,wi4.w};
#pragma unroll
            for (int i = 0; i < 8; i++)
#pragma unroll
                for (int j = 0; j < 4; j++) {
                    cr[i][j] = fmaf(ar[i], br[j], cr[i][j]);
                    cr[i][j] = fmaf(-ai[i], bi[j], cr[i][j]);
                    ci[i][j] = fmaf(ai[i], br[j], ci[i][j]);
                    ci[i][j] = fmaf(ar[i], bi[j], ci[i][j]);
                }
        }
        __syncthreads();
    }
    float4 br4 = *(const float4*)(bR + bn + tx*4);
    float4 bi4 = *(const float4*)(bI + bn + tx*4);
#pragma unroll
    for (int i = 0; i < 8; i++) {
        const size_t row = (size_t)(bm + ty*8 + i);
        float4 o, p;
        o.x = cr[i][0] + br4.x; o.y = cr[i][1] + br4.y;
        o.z = cr[i][2] + br4.z; o.w = cr[i][3] + br4.w;
        p.x = ci[i][0] + bi4.x; p.y = ci[i][1] + bi4.y;
        p.z = ci[i][2] + bi4.z; p.w = ci[i][3] + bi4.w;
        *(float4*)(Cr + row*256 + bn + tx*4) = o;
        *(float4*)(Ci + row*256 + bn + tx*4) = p;
    }
}

// ============================================================================
// Split-bf16 conversion -> row of 1536 bf16 (6 segments of 256).
// Q mode: [hr | lr | hr | hi | li | hi]
// K mode: [hr | hr | lr | hi | hi | li]
// Product per component: hh + lh + hl (exact to ~2^-18).
// ============================================================================
__device__ __forceinline__ uint32_t pack_bf2(float a, float b) {
    __nv_bfloat162 t = __floats2bfloat162_rn(a, b);
    return *(uint32_t*)&t;
}
__global__ __launch_bounds__(256) void convert_split(
    const float* __restrict__ Xr, const float* __restrict__ Xi,
    __nv_bfloat16* __restrict__ cat, int isK)
{
    const size_t t = (size_t)blockIdx.x * 256 + threadIdx.x;
    const size_t row = t >> 6;
    const int c = (int)(t & 63) << 2;
    float4 xr = *(const float4*)(Xr + row*256 + c);
    float4 xi = *(const float4*)(Xi + row*256 + c);
    float hr[4] = {xr.x, xr.y, xr.z, xr.w};
    float hi[4] = {xi.x, xi.y, xi.z, xi.w};
    float lr[4], li[4], hhr[4], hhi[4];
#pragma unroll
    for (int j = 0; j < 4; j++) {
        __nv_bfloat16 h = __float2bfloat16(hr[j]);
        hhr[j] = __bfloat162float(h); lr[j] = hr[j] - hhr[j];
        __nv_bfloat16 g = __float2bfloat16(hi[j]);
        hhi[j] = __bfloat162float(g); li[j] = hi[j] - hhi[j];
    }
    uint32_t* out = (uint32_t*)(cat + row * KCAT);
    const int c2 = c >> 1;
    const int seg_hr2 = isK ? 1 : 2;
    const int seg_lr  = isK ? 2 : 1;
    const int seg_hi2 = isK ? 4 : 5;
    const int seg_li  = isK ? 5 : 4;
    uint32_t phr0 = pack_bf2(hhr[0], hhr[1]), phr1 = pack_bf2(hhr[2], hhr[3]);
    uint32_t plr0 = pack_bf2(lr[0],  lr[1]),  plr1 = pack_bf2(lr[2],  lr[3]);
    uint32_t phi0 = pack_bf2(hhi[0], hhi[1]), phi1 = pack_bf2(hhi[2], hhi[3]);
    uint32_t pli0 = pack_bf2(li[0],  li[1]),  pli1 = pack_bf2(li[2],  li[3]);
    out[c2]                 = phr0; out[c2+1]                 = phr1;
    out[seg_hr2*128 + c2]   = phr0; out[seg_hr2*128 + c2+1]   = phr1;
    out[seg_lr*128 + c2]    = plr0; out[seg_lr*128 + c2+1]    = plr1;
    out[3*128 + c2]         = phi0; out[3*128 + c2+1]         = phi1;
    out[seg_hi2*128 + c2]   = phi0; out[seg_hi2*128 + c2+1]   = phi1;
    out[seg_li*128 + c2]    = pli0; out[seg_li*128 + c2+1]    = pli1;
}

// ============================================================================
// Transpose V fp32 [bh][k=2048][n=256] -> fp16 [bh][n=256][k=2048]
// ============================================================================
__global__ void transpose_v(
    const float* __restrict__ Vr, const float* __restrict__ Vi,
    __half* __restrict__ Vtr, __half* __restrict__ Vti)
{
    __shared__ float tr[32][33], ti[32][33];
    const int head = blockIdx.z;
    const int k0 = blockIdx.x * 32, n0 = blockIdx.y * 32;
    const int tx = threadIdx.x, ty = threadIdx.y;
    const size_t ibase = (size_t)head * T_SEQ * 256;
#pragma unroll
    for (int i = 0; i < 32; i += 8) {
        tr[ty+i][tx] = Vr[ibase + (size_t)(k0+ty+i)*256 + n0+tx];
        ti[ty+i][tx] = Vi[ibase + (size_t)(k0+ty+i)*256 + n0+tx];
    }
    __syncthreads();
    const size_t obase = ((size_t)head * 256 + n0) * T_SEQ + k0;
#pragma unroll
    for (int i = 0; i < 32; i += 8) {
        Vtr[obase + (size_t)(ty+i)*T_SEQ + tx] = __float2half(tr[tx][ty+i]);
        Vti[obase + (size_t)(ty+i)*T_SEQ + tx] = __float2half(ti[tx][ty+i]);
    }
}

// ============================================================================
// Row softmax: read fp32 scores, write fp16 attn
// ============================================================================
__global__ __launch_bounds__(256) void softmax_rows(
    const float* __restrict__ S, __half* __restrict__ A)
{
    const float* p = S + (size_t)blockIdx.x * T_SEQ;
    __half* ap = A + (size_t)blockIdx.x * T_SEQ;
    const int tid = threadIdx.x;
    float v[8];
    float m = -3.4e38f;
#pragma unroll
    for (int r = 0; r < 8; r++) { v[r] = p[tid + (r << 8)]; m = fmaxf(m, v[r]); }
#pragma unroll
    for (int o = 16; o > 0; o >>= 1) m = fmaxf(m, __shfl_xor_sync(0xffffffffu, m, o));
    __shared__ float red[8];
    if ((tid & 31) == 0) red[tid >> 5] = m;
    __syncthreads();
    m = red[0];
#pragma unroll
    for (int w = 1; w < 8; w++) m = fmaxf(m, red[w]);
    float sum = 0.f;
#pragma unroll
    for (int r = 0; r < 8; r++) { v[r] = __expf(v[r] - m); sum += v[r]; }
#pragma unroll
    for (int o = 16; o > 0; o >>= 1) sum += __shfl_xor_sync(0xffffffffu, sum, o);
    __syncthreads();
    if ((tid & 31) == 0) red[tid >> 5] = sum;
    __syncthreads();
    sum = 0.f;
#pragma unroll
    for (int w = 0; w < 8; w++) sum += red[w];
    const float inv = 1.f / sum;
#pragma unroll
    for (int r = 0; r < 8; r++) ap[tid + (r << 8)] = __float2half(v[r] * inv);
}

// ============================================================================
// Gate GEMM: G = sigmoid( mag(Or,Oi) @ W^T + bias )
// ============================================================================
__global__ __launch_bounds__(256) void gate_gemm(
    const float* __restrict__ Or, const float* __restrict__ Oi,
    const float* __restrict__ W, const float* __restrict__ bias,
    float* __restrict__ G)
{
    __shared__ float As[8][132], Bs[8][68];
    const int bm = blockIdx.x * 128, bn = blockIdx.y * 64;
    const int tid = threadIdx.x;
    const int ty = tid >> 4, tx = tid & 15;
    const int lrow = tid >> 1;
    const int lk   = (tid & 1) << 2;
    const int brow = (tid & 127) >> 1;

    float c[8][4];
#pragma unroll
    for (int i = 0; i < 8; i++)
#pragma unroll
        for (int j = 0; j < 4; j++) c[i][j] = 0.f;

    for (int k0 = 0; k0 < 256; k0 += 8) {
        float4 o1 = *(const float4*)(Or + (size_t)(bm + lrow) * 256 + k0 + lk);
        float4 o2 = *(const float4*)(Oi + (size_t)(bm + lrow) * 256 + k0 + lk);
        As[lk+0][lrow] = sqrtf(o1.x*o1.x + o2.x*o2.x + EPS_F);
        As[lk+1][lrow] = sqrtf(o1.y*o1.y + o2.y*o2.y + EPS_F);
        As[lk+2][lrow] = sqrtf(o1.z*o1.z + o2.z*o2.z + EPS_F);
        As[lk+3][lrow] = sqrtf(o1.w*o1.w + o2.w*o2.w + EPS_F);
        if (tid < 128) {
            float4 w = *(const float4*)(W + (size_t)(bn + brow) * 256 + k0 + lk);
            Bs[lk+0][brow] = w.x; Bs[lk+1][brow] = w.y;
            Bs[lk+2][brow] = w.z; Bs[lk+3][brow] = w.w;
        }
        __syncthreads();
#pragma unroll
        for (int kk = 0; kk < 8; kk++) {
            float4 a0 = *(const float4*)&As[kk][ty*8];
            float4 a1 = *(const float4*)&As[kk][ty*8+4];
            float4 b4 = *(const float4*)&Bs[kk][tx*4];
            float av[8] = {a0.x,a0.y,a0.z,a0.w,a1.x,a1.y,a1.z,a1.w};
            float bv[4] = {b4.x,b4.y,b4.z,b4.w};
#pragma unroll
            for (int i = 0; i < 8; i++)
#pragma unroll
                for (int j = 0; j < 4; j++)
                    c[i][j] = fmaf(av[i], bv[j], c[i][j]);
        }
        __syncthreads();
    }
    float4 b4 = *(const float4*)(bias + bn + tx*4);
#pragma unroll
    for (int i = 0; i < 8; i++) {
        const size_t row = (size_t)(bm + ty*8 + i);
        float4 g;
        g.x = 1.f / (1.f + __expf(-(c[i][0] + b4.x)));
        g.y = 1.f / (1.f + __expf(-(c[i][1] + b4.y)));
        g.z = 1.f / (1.f + __expf(-(c[i][2] + b4.z)));
        g.w = 1.f / (1.f + __expf(-(c[i][3] + b4.w)));
        *(float4*)(G + row*256 + bn + tx*4) = g;
    }
}

// ============================================================================
__global__ __launch_bounds__(256) void finalize_kernel(
    const float* __restrict__ Or, const float* __restrict__ Oi,
    const float* __restrict__ G, float* __restrict__ out)
{
    const size_t i = ((size_t)blockIdx.x * 256 + threadIdx.x) * 4;
    float4 a = *(const float4*)(Or + i);
    float4 b = *(const float4*)(Oi + i);
    float4 g = *(const float4*)(G + i);
    float4 x, y;
    x.x = a.x*g.x; x.y = a.y*g.y; x.z = a.z*g.z; x.w = a.w*g.w;
    y.x = b.x*g.x; y.y = b.y*g.y; y.z = b.z*g.z; y.w = b.w*g.w;
    *(float4*)(out + i) = x;
    *(float4*)(out + (size_t)M_TOT * D_MOD + i) = y;
}

// ============================================================================
extern "C" void kernel_launch(void* const* d_in, const int* in_sizes, int n_in,
                              void* d_out, int out_size)
{
    const float* q_in_r  = (const float*)d_in[0];
    const float* q_in_i  = (const float*)d_in[1];
    const float* kv_in_r = (const float*)d_in[2];
    const float* kv_in_i = (const float*)d_in[3];
    const float* q_wr = (const float*)d_in[4];
    const float* q_wi = (const float*)d_in[5];
    const float* q_br = (const float*)d_in[6];
    const float* q_bi = (const float*)d_in[7];
    const float* k_wr = (const float*)d_in[8];
    const float* k_wi = (const float*)d_in[9];
    const float* k_br = (const float*)d_in[10];
    const float* k_bi = (const float*)d_in[11];
    const float* v_wr = (const float*)d_in[12];
    const float* v_wi = (const float*)d_in[13];
    const float* v_br = (const float*)d_in[14];
    const float* v_bi = (const float*)d_in[15];
    const float* o_wr = (const float*)d_in[16];
    const float* o_wi = (const float*)d_in[17];
    const float* o_br = (const float*)d_in[18];
    const float* o_bi = (const float*)d_in[19];
    const float* gate_w = (const float*)d_in[20];
    const float* gate_b = (const float*)d_in[21];

    float *p_qr, *p_qi, *p_kr, *p_ki, *p_vr, *p_vi;
    float *p_cr, *p_ci, *p_or, *p_oi, *p_g, *p_sc;
    __half *p_attn, *p_vtr, *p_vti;
    __nv_bfloat16 *p_qcat, *p_kcat;
    cudaGetSymbolAddress((void**)&p_qr, g_qr);
    cudaGetSymbolAddress((void**)&p_qi, g_qi);
    cudaGetSymbolAddress((void**)&p_kr, g_kr);
    cudaGetSymbolAddress((void**)&p_ki, g_ki);
    cudaGetSymbolAddress((void**)&p_vr, g_vr);
    cudaGetSymbolAddress((void**)&p_vi, g_vi);
    cudaGetSymbolAddress((void**)&p_cr, g_cr);
    cudaGetSymbolAddress((void**)&p_ci, g_ci);
    cudaGetSymbolAddress((void**)&p_or, g_outr);
    cudaGetSymbolAddress((void**)&p_oi, g_outi);
    cudaGetSymbolAddress((void**)&p_g,  g_gate);
    cudaGetSymbolAddress((void**)&p_sc, g_sc);
    cudaGetSymbolAddress((void**)&p_attn, g_attn);
    cudaGetSymbolAddress((void**)&p_qcat, g_qcat);
    cudaGetSymbolAddress((void**)&p_kcat, g_kcat);
    cudaGetSymbolAddress((void**)&p_vtr, g_vtr);
    cudaGetSymbolAddress((void**)&p_vti, g_vti);

    const dim3 tpb(256);
    const dim3 proj_grid(M_TOT / 128, D_MOD / 64);

    // Projections (fp32 SIMT)
    cgemm_nt<<<proj_grid, tpb>>>(q_in_r, q_in_i, q_wr, q_wi, q_br, q_bi, p_qr, p_qi);
    cgemm_nt<<<proj_grid, tpb>>>(kv_in_r, kv_in_i, k_wr, k_wi, k_br, k_bi, p_kr, p_ki);
    cgemm_nt<<<proj_grid, tpb>>>(kv_in_r, kv_in_i, v_wr, v_wi, v_br, v_bi, p_vr, p_vi);

    // Convert for tensor cores
    convert_split<<<16384, tpb>>>(p_qr, p_qi, p_qcat, 0);
    convert_split<<<16384, tpb>>>(p_kr, p_ki, p_kcat, 1);
    transpose_v<<<dim3(T_SEQ/32, D_MOD/32, N_BH), dim3(32, 8)>>>(p_vr, p_vi, p_vtr, p_vti);

    // Attention on mma.sync tensor cores
    score_mma<<<dim3(16, 16, N_BH), tpb>>>(p_qcat, p_kcat, p_sc);
    softmax_rows<<<(unsigned)(N_BH * T_SEQ), tpb>>>(p_sc, p_attn);
    ctx_mma<<<dim3(16, 2, 2 * N_BH), tpb>>>(p_attn, p_vtr, p_vti, p_cr, p_ci);

    // Output projection + gating (fp32 SIMT)
    cgemm_nt<<<proj_grid, tpb>>>(p_cr, p_ci, o_wr, o_wi, o_br, o_bi, p_or, p_oi);
    gate_gemm<<<proj_grid, tpb>>>(p_or, p_oi, gate_w, gate_b, p_g);
    finalize_kernel<<<(M_TOT * D_MOD) / (256 * 4), tpb>>>(p_or, p_oi, p_g, (float*)d_out);
}

// round 12
// speedup vs baseline: 1.8723x; 1.0980x over previous
#include <cuda_runtime.h>
#include <cuda_bf16.h>
#include <cuda_fp16.h>
#include <math.h>
#include <stdint.h>

#define T_SEQ 2048
#define D_MOD 256
#define N_BH  32
#define M_TOT (N_BH * T_SEQ)   /* 65536 */
#define EPS_F 1e-8f
#define KCAT  1024              /* split-fp16 concatenated K for scores */

// ---- scratch (device globals; no runtime allocation allowed) ----
__device__ float g_qr[M_TOT * D_MOD];
__device__ float g_qi[M_TOT * D_MOD];
__device__ float g_kr[M_TOT * D_MOD];
__device__ float g_ki[M_TOT * D_MOD];
__device__ float g_vr[M_TOT * D_MOD];
__device__ float g_vi[M_TOT * D_MOD];
__device__ float g_cr[M_TOT * D_MOD];
__device__ float g_ci[M_TOT * D_MOD];
__device__ float g_outr[M_TOT * D_MOD];
__device__ float g_outi[M_TOT * D_MOD];
__device__ float g_gate[M_TOT * D_MOD];
__device__ float g_sc[(size_t)N_BH * T_SEQ * T_SEQ];          /* 512 MB fp32 scores */
__device__ __half g_attn[(size_t)N_BH * T_SEQ * T_SEQ];       /* 256 MB fp16 attn  */
__device__ __half g_qcat[(size_t)M_TOT * KCAT];               /* 128 MB split-fp16 */
__device__ __half g_kcat[(size_t)M_TOT * KCAT];               /* 128 MB split-fp16 */
__device__ __half g_vtr[(size_t)N_BH * D_MOD * T_SEQ];        /* 32 MB V^T fp16    */
__device__ __half g_vti[(size_t)N_BH * D_MOD * T_SEQ];        /* 32 MB V^T fp16    */

// ============================================================================
// helpers
// ============================================================================
__device__ __forceinline__ uint32_t smem_to_u32(const void* smem_ptr) {
    uint32_t addr;
    asm("{ .reg .u64 tmp; cvta.to.shared.u64 tmp, %1; cvt.u32.u64 %0, tmp; }"
        : "=r"(addr) : "l"(smem_ptr));
    return addr;
}
__device__ __forceinline__ void cp16(uint32_t smem_addr, const void* gptr) {
    asm volatile("cp.async.cg.shared.global [%0], [%1], 16;"
                 :: "r"(smem_addr), "l"(gptr) : "memory");
}
__device__ __forceinline__ void ldsm_x4(uint32_t* r, uint32_t addr) {
    asm volatile("ldmatrix.sync.aligned.m8n8.x4.shared.b16 {%0,%1,%2,%3}, [%4];"
                 : "=r"(r[0]), "=r"(r[1]), "=r"(r[2]), "=r"(r[3]) : "r"(addr));
}
__device__ __forceinline__ void ldsm_x2(uint32_t* r, uint32_t addr) {
    asm volatile("ldmatrix.sync.aligned.m8n8.x2.shared.b16 {%0,%1}, [%2];"
                 : "=r"(r[0]), "=r"(r[1]) : "r"(addr));
}
__device__ __forceinline__ void mma_bf16(float* d, const uint32_t* a, const uint32_t* b) {
    asm volatile(
        "mma.sync.aligned.m16n8k16.row.col.f32.bf16.bf16.f32 "
        "{%0,%1,%2,%3}, {%4,%5,%6,%7}, {%8,%9}, {%0,%1,%2,%3};"
        : "+f"(d[0]), "+f"(d[1]), "+f"(d[2]), "+f"(d[3])
        : "r"(a[0]), "r"(a[1]), "r"(a[2]), "r"(a[3]), "r"(b[0]), "r"(b[1]));
}
__device__ __forceinline__ void mma_f16(float* d, const uint32_t* a, const uint32_t* b) {
    asm volatile(
        "mma.sync.aligned.m16n8k16.row.col.f32.f16.f16.f32 "
        "{%0,%1,%2,%3}, {%4,%5,%6,%7}, {%8,%9}, {%0,%1,%2,%3};"
        : "+f"(d[0]), "+f"(d[1]), "+f"(d[2]), "+f"(d[3])
        : "r"(a[0]), "r"(a[1]), "r"(a[2]), "r"(a[3]), "r"(b[0]), "r"(b[1]));
}

// ============================================================================
// Generic 128x128 NT tile GEMM on mma.sync (A,B K-major 16-bit), fp32 out.
// 256 threads = 8 warps in 2(m) x 4(n); warp tile 64x32; Kblk=32.
// 3-stage cp.async pipeline in dynamic smem: stage = 20480 B (A 10240 + B 10240),
// total 61440 B. Stage-reuse distance 3; end-of-iter barrier protects reuse.
// ============================================================================
#define SBUF_B   10240u   /* bytes per matrix per stage: 128*40*2 */
#define STAGE_B  20480u   /* bytes per stage (A+B) */

template<bool BF16, int KTOT>
__device__ __forceinline__ void gemm_mma_body(
    const uint16_t* __restrict__ Ag, const uint16_t* __restrict__ Bg,
    float* __restrict__ Cg, int ldc, float scale)
{
    extern __shared__ uint16_t sh16[];
    const uint32_t base = smem_to_u32(sh16);
    const int tid = threadIdx.x;
    const int wid = tid >> 5, lane = tid & 31;
    const int wm = wid & 1, wn = wid >> 1;

    float acc[4][4][4];
#pragma unroll
    for (int i = 0; i < 4; i++)
#pragma unroll
        for (int j = 0; j < 4; j++)
#pragma unroll
            for (int v = 0; v < 4; v++) acc[i][j][v] = 0.f;

    const int c0 = tid, c1 = tid + 256;
    const int r0 = c0 >> 2, o0 = (c0 & 3) * 8;
    const int r1 = c1 >> 2, o1 = (c1 & 3) * 8;
    const uint32_t s0 = (uint32_t)((r0 * 40 + o0) * 2);
    const uint32_t s1 = (uint32_t)((r1 * 40 + o1) * 2);

    constexpr int NIT = KTOT / 32;

    // stage issue: 128x32 of A and B into stage buffer
#define ISSUE_STAGE(stg, itk) do {                                          \
        const uint32_t sb_ = base + (uint32_t)(stg) * STAGE_B;              \
        const int k0_ = (itk) * 32;                                         \
        cp16(sb_ + s0,          Ag + (size_t)r0 * KTOT + k0_ + o0);         \
        cp16(sb_ + SBUF_B + s0, Bg + (size_t)r0 * KTOT + k0_ + o0);         \
        cp16(sb_ + s1,          Ag + (size_t)r1 * KTOT + k0_ + o1);         \
        cp16(sb_ + SBUF_B + s1, Bg + (size_t)r1 * KTOT + k0_ + o1);         \
        asm volatile("cp.async.commit_group;" ::: "memory");                \
    } while (0)

    ISSUE_STAGE(0, 0);
    if (NIT > 1) ISSUE_STAGE(1, 1);

    for (int it = 0; it < NIT; it++) {
        if (it + 2 < NIT) {
            ISSUE_STAGE((it + 2) % 3, it + 2);
            asm volatile("cp.async.wait_group 2;" ::: "memory");
        } else if (it + 1 < NIT) {
            asm volatile("cp.async.wait_group 1;" ::: "memory");
        } else {
            asm volatile("cp.async.wait_group 0;" ::: "memory");
        }
        __syncthreads();
        const uint32_t ab = base + (uint32_t)((it % 3)) * STAGE_B;
        const uint32_t bb = ab + SBUF_B;
#pragma unroll
        for (int ks = 0; ks < 32; ks += 16) {
            uint32_t af[4][4], bf[4][2];
            const int ar = lane & 15, ac = ks + ((lane >> 4) << 3);
#pragma unroll
            for (int i = 0; i < 4; i++)
                ldsm_x4(af[i], ab + (uint32_t)(((wm * 64 + i * 16 + ar) * 40 + ac) << 1));
            const int l = lane & 15;
            const int br_ = l & 7, bc = ks + ((l >> 3) << 3);
#pragma unroll
            for (int j = 0; j < 4; j++)
                ldsm_x2(bf[j], bb + (uint32_t)(((wn * 32 + j * 8 + br_) * 40 + bc) << 1));
#pragma unroll
            for (int i = 0; i < 4; i++)
#pragma unroll
                for (int j = 0; j < 4; j++) {
                    if (BF16) mma_bf16(acc[i][j], af[i], bf[j]);
                    else      mma_f16(acc[i][j], af[i], bf[j]);
                }
        }
        __syncthreads();
    }
#undef ISSUE_STAGE

#pragma unroll
    for (int i = 0; i < 4; i++) {
        const int row = wm * 64 + i * 16 + (lane >> 2);
#pragma unroll
        for (int j = 0; j < 4; j++) {
            const int col = wn * 32 + j * 8 + (lane & 3) * 2;
            float2 v0 = make_float2(acc[i][j][0] * scale, acc[i][j][1] * scale);
            float2 v1 = make_float2(acc[i][j][2] * scale, acc[i][j][3] * scale);
            *(float2*)(Cg + (size_t)row * ldc + col) = v0;
            *(float2*)(Cg + (size_t)(row + 8) * ldc + col) = v1;
        }
    }
}

// Scores: S = Qcat @ Kcat^T * scale, K=1024 split-fp16
// (Q=[hr|lr|hi|li], K=[hr|hr|hi|hi]; dropped q*k_lo term ~2.8e-4 on scores)
__global__ __launch_bounds__(256) void score_mma(
    const __half* __restrict__ Q, const __half* __restrict__ K,
    float* __restrict__ S)
{
    const int head = blockIdx.z;
    const int bm = blockIdx.x * 128, bn = blockIdx.y * 128;
    const uint16_t* A = (const uint16_t*)(Q + ((size_t)head * T_SEQ + bm) * KCAT);
    const uint16_t* B = (const uint16_t*)(K + ((size_t)head * T_SEQ + bn) * KCAT);
    float* C = S + ((size_t)head * T_SEQ + bm) * T_SEQ + bn;
    gemm_mma_body<false, KCAT>(A, B, C, T_SEQ, 0.0625f);
}

// Context: C[r|i] = attn @ Vt^T, fp16, K=2048. grid (16, 2, 64) z=head*2+part
__global__ __launch_bounds__(256) void ctx_mma(
    const __half* __restrict__ Attn, const __half* __restrict__ Vtr,
    const __half* __restrict__ Vti,
    float* __restrict__ Cr, float* __restrict__ Ci)
{
    const int bz = blockIdx.z;
    const int head = bz >> 1, part = bz & 1;
    const int bm = blockIdx.x * 128, bn = blockIdx.y * 128;
    const uint16_t* A = (const uint16_t*)(Attn + ((size_t)head * T_SEQ + bm) * T_SEQ);
    const __half* Vt = part ? Vti : Vtr;
    const uint16_t* B = (const uint16_t*)(Vt + ((size_t)head * D_MOD + bn) * T_SEQ);
    float* Cbase = part ? Ci : Cr;
    float* C = Cbase + ((size_t)head * T_SEQ + bm) * D_MOD + bn;
    gemm_mma_body<false, T_SEQ>(A, B, C, D_MOD, 1.0f);
}

// ============================================================================
// Complex GEMM NT (fp32 SIMT — projections):
// Cr = Ar*Wr^T - Ai*Wi^T + bR ; Ci = Ai*Wr^T + Ar*Wi^T + bI
// ============================================================================
__global__ __launch_bounds__(256) void cgemm_nt(
    const float* __restrict__ Ar, const float* __restrict__ Ai,
    const float* __restrict__ Wr, const float* __restrict__ Wi,
    const float* __restrict__ bR, const float* __restrict__ bI,
    float* __restrict__ Cr, float* __restrict__ Ci)
{
    __shared__ float Asr[8][132], Asi[8][132], Bsr[8][68], Bsi[8][68];
    const int tid = threadIdx.x;
    const int bm = blockIdx.x * 128;
    const int bn = blockIdx.y * 64;
    const int ty = tid >> 4, tx = tid & 15;
    const int lrow = tid >> 1;
    const int lk   = (tid & 1) << 2;
    const int brow = (tid & 127) >> 1;
    const float* Wsel = (tid < 128) ? Wr : Wi;
    float* bdst = (tid < 128) ? &Bsr[0][0] : &Bsi[0][0];

    float cr[8][4], ci[8][4];
#pragma unroll
    for (int i = 0; i < 8; i++)
#pragma unroll
        for (int j = 0; j < 4; j++) { cr[i][j] = 0.f; ci[i][j] = 0.f; }

    for (int k0 = 0; k0 < 256; k0 += 8) {
        float4 a0 = *(const float4*)(Ar + (size_t)(bm + lrow) * 256 + k0 + lk);
        float4 a1 = *(const float4*)(Ai + (size_t)(bm + lrow) * 256 + k0 + lk);
        float4 w  = *(const float4*)(Wsel + (size_t)(bn + brow) * 256 + k0 + lk);
        Asr[lk+0][lrow] = a0.x; Asr[lk+1][lrow] = a0.y;
        Asr[lk+2][lrow] = a0.z; Asr[lk+3][lrow] = a0.w;
        Asi[lk+0][lrow] = a1.x; Asi[lk+1][lrow] = a1.y;
        Asi[lk+2][lrow] = a1.z; Asi[lk+3][lrow] = a1.w;
        bdst[(lk+0)*68 + brow] = w.x; bdst[(lk+1)*68 + brow] = w.y;
        bdst[(lk+2)*68 + brow] = w.z; bdst[(lk+3)*68 + brow] = w.w;
        __syncthreads();
#pragma unroll
        for (int kk = 0; kk < 8; kk++) {
            float4 r0 = *(const float4*)&Asr[kk][ty*8];
            float4 r1 = *(const float4*)&Asr[kk][ty*8+4];
            float4 i0 = *(const float4*)&Asi[kk][ty*8];
            float4 i1 = *(const float4*)&Asi[kk][ty*8+4];
            float4 wr4 = *(const float4*)&Bsr[kk][tx*4];
            float4 wi4 = *(const float4*)&Bsi[kk][tx*4];
            float ar[8] = {r0.x,r0.y,r0.z,r0.w,r1.x,r1.y,r1.z,r1.w};
            float ai[8] = {i0.x,i0.y,i0.z,i0.w,i1.x,i1.y,i1.z,i1.w};
            float br[4] = {wr4.x,wr4.y,wr4.z,wr4.w};
            float bi[4] = {wi4.x,wi4.y,wi4.z,wi4.w};
#pragma unroll
            for (int i = 0; i < 8; i++)
#pragma unroll
                for (int j = 0; j < 4; j++) {
                    cr[i][j] = fmaf(ar[i], br[j], cr[i][j]);
                    cr[i][j] = fmaf(-ai[i], bi[j], cr[i][j]);
                    ci[i][j] = fmaf(ai[i], br[j], ci[i][j]);
                    ci[i][j] = fmaf(ar[i], bi[j], ci[i][j]);
                }
        }
        __syncthreads();
    }
    float4 br4 = *(const float4*)(bR + bn + tx*4);
    float4 bi4 = *(const float4*)(bI + bn + tx*4);
#pragma unroll
    for (int i = 0; i < 8; i++) {
        const size_t row = (size_t)(bm + ty*8 + i);
        float4 o, p;
        o.x = cr[i][0] + br4.x; o.y = cr[i][1] + br4.y;
        o.z = cr[i][2] + br4.z; o.w = cr[i][3] + br4.w;
        p.x = ci[i][0] + bi4.x; p.y = ci[i][1] + bi4.y;
        p.z = ci[i][2] + bi4.z; p.w = ci[i][3] + bi4.w;
        *(float4*)(Cr + row*256 + bn + tx*4) = o;
        *(float4*)(Ci + row*256 + bn + tx*4) = p;
    }
}

// ============================================================================
// Split-fp16 conversion -> row of 1024 fp16 (4 segments of 256).
// Q mode: [hi(r) | lo(r) | hi(i) | lo(i)]
// K mode: [hi(r) | hi(r) | hi(i) | hi(i)]
// Score = qr*kh_r + qi*kh_i; dropped q*k_lo ~ 2^-12 relative.
// ============================================================================
__device__ __forceinline__ uint32_t pack_h2(float a, float b) {
    __half2 t = __floats2half2_rn(a, b);
    return *(uint32_t*)&t;
}
__global__ __launch_bounds__(256) void convert_split(
    const float* __restrict__ Xr, const float* __restrict__ Xi,
    __half* __restrict__ cat, int isK)
{
    const size_t t = (size_t)blockIdx.x * 256 + threadIdx.x;
    const size_t row = t >> 6;
    const int c = (int)(t & 63) << 2;
    float4 xr = *(const float4*)(Xr + row*256 + c);
    float4 xi = *(const float4*)(Xi + row*256 + c);
    float vr[4] = {xr.x, xr.y, xr.z, xr.w};
    float vi[4] = {xi.x, xi.y, xi.z, xi.w};
    float hr[4], lr[4], hi[4], li[4];
#pragma unroll
    for (int j = 0; j < 4; j++) {
        __half h = __float2half_rn(vr[j]);
        hr[j] = __half2float(h); lr[j] = vr[j] - hr[j];
        __half g = __float2half_rn(vi[j]);
        hi[j] = __half2float(g); li[j] = vi[j] - hi[j];
    }
    uint32_t* out = (uint32_t*)(cat + row * KCAT);
    const int c2 = c >> 1;
    uint32_t phr0 = pack_h2(hr[0], hr[1]), phr1 = pack_h2(hr[2], hr[3]);
    uint32_t phi0 = pack_h2(hi[0], hi[1]), phi1 = pack_h2(hi[2], hi[3]);
    if (isK) {
        out[c2]           = phr0; out[c2+1]           = phr1;
        out[128 + c2]     = phr0; out[128 + c2+1]     = phr1;
        out[256 + c2]     = phi0; out[256 + c2+1]     = phi1;
        out[384 + c2]     = phi0; out[384 + c2+1]     = phi1;
    } else {
        uint32_t plr0 = pack_h2(lr[0], lr[1]), plr1 = pack_h2(lr[2], lr[3]);
        uint32_t pli0 = pack_h2(li[0], li[1]), pli1 = pack_h2(li[2], li[3]);
        out[c2]           = phr0; out[c2+1]           = phr1;
        out[128 + c2]     = plr0; out[128 + c2+1]     = plr1;
        out[256 + c2]     = phi0; out[256 + c2+1]     = phi1;
        out[384 + c2]     = pli0; out[384 + c2+1]     = pli1;
    }
}

// ============================================================================
// Transpose V fp32 [bh][k=2048][n=256] -> fp16 [bh][n=256][k=2048]
// ============================================================================
__global__ void transpose_v(
    const float* __restrict__ Vr, const float* __restrict__ Vi,
    __half* __restrict__ Vtr, __half* __restrict__ Vti)
{
    __shared__ float tr[32][33], ti[32][33];
    const int head = blockIdx.z;
    const int k0 = blockIdx.x * 32, n0 = blockIdx.y * 32;
    const int tx = threadIdx.x, ty = threadIdx.y;
    const size_t ibase = (size_t)head * T_SEQ * 256;
#pragma unroll
    for (int i = 0; i < 32; i += 8) {
        tr[ty+i][tx] = Vr[ibase + (size_t)(k0+ty+i)*256 + n0+tx];
        ti[ty+i][tx] = Vi[ibase + (size_t)(k0+ty+i)*256 + n0+tx];
    }
    __syncthreads();
    const size_t obase = ((size_t)head * 256 + n0) * T_SEQ + k0;
#pragma unroll
    for (int i = 0; i < 32; i += 8) {
        Vtr[obase + (size_t)(ty+i)*T_SEQ + tx] = __float2half(tr[tx][ty+i]);
        Vti[obase + (size_t)(ty+i)*T_SEQ + tx] = __float2half(ti[tx][ty+i]);
    }
}

// ============================================================================
// Row softmax: read fp32 scores, write fp16 attn
// ============================================================================
__global__ __launch_bounds__(256) void softmax_rows(
    const float* __restrict__ S, __half* __restrict__ A)
{
    const float* p = S + (size_t)blockIdx.x * T_SEQ;
    __half* ap = A + (size_t)blockIdx.x * T_SEQ;
    const int tid = threadIdx.x;
    float v[8];
    float m = -3.4e38f;
#pragma unroll
    for (int r = 0; r < 8; r++) { v[r] = p[tid + (r << 8)]; m = fmaxf(m, v[r]); }
#pragma unroll
    for (int o = 16; o > 0; o >>= 1) m = fmaxf(m, __shfl_xor_sync(0xffffffffu, m, o));
    __shared__ float red[8];
    if ((tid & 31) == 0) red[tid >> 5] = m;
    __syncthreads();
    m = red[0];
#pragma unroll
    for (int w = 1; w < 8; w++) m = fmaxf(m, red[w]);
    float sum = 0.f;
#pragma unroll
    for (int r = 0; r < 8; r++) { v[r] = __expf(v[r] - m); sum += v[r]; }
#pragma unroll
    for (int o = 16; o > 0; o >>= 1) sum += __shfl_xor_sync(0xffffffffu, sum, o);
    __syncthreads();
    if ((tid & 31) == 0) red[tid >> 5] = sum;
    __syncthreads();
    sum = 0.f;
#pragma unroll
    for (int w = 0; w < 8; w++) sum += red[w];
    const float inv = 1.f / sum;
#pragma unroll
    for (int r = 0; r < 8; r++) ap[tid + (r << 8)] = __float2half(v[r] * inv);
}

// ============================================================================
// Gate GEMM: G = sigmoid( mag(Or,Oi) @ W^T + bias )
// ============================================================================
__global__ __launch_bounds__(256) void gate_gemm(
    const float* __restrict__ Or, const float* __restrict__ Oi,
    const float* __restrict__ W, const float* __restrict__ bias,
    float* __restrict__ G)
{
    __shared__ float As[8][132], Bs[8][68];
    const int bm = blockIdx.x * 128, bn = blockIdx.y * 64;
    const int tid = threadIdx.x;
    const int ty = tid >> 4, tx = tid & 15;
    const int lrow = tid >> 1;
    const int lk   = (tid & 1) << 2;
    const int brow = (tid & 127) >> 1;

    float c[8][4];
#pragma unroll
    for (int i = 0; i < 8; i++)
#pragma unroll
        for (int j = 0; j < 4; j++) c[i][j] = 0.f;

    for (int k0 = 0; k0 < 256; k0 += 8) {
        float4 o1 = *(const float4*)(Or + (size_t)(bm + lrow) * 256 + k0 + lk);
        float4 o2 = *(const float4*)(Oi + (size_t)(bm + lrow) * 256 + k0 + lk);
        As[lk+0][lrow] = sqrtf(o1.x*o1.x + o2.x*o2.x + EPS_F);
        As[lk+1][lrow] = sqrtf(o1.y*o1.y + o2.y*o2.y + EPS_F);
        As[lk+2][lrow] = sqrtf(o1.z*o1.z + o2.z*o2.z + EPS_F);
        As[lk+3][lrow] = sqrtf(o1.w*o1.w + o2.w*o2.w + EPS_F);
        if (tid < 128) {
            float4 w = *(const float4*)(W + (size_t)(bn + brow) * 256 + k0 + lk);
            Bs[lk+0][brow] = w.x; Bs[lk+1][brow] = w.y;
            Bs[lk+2][brow] = w.z; Bs[lk+3][brow] = w.w;
        }
        __syncthreads();
#pragma unroll
        for (int kk = 0; kk < 8; kk++) {
            float4 a0 = *(const float4*)&As[kk][ty*8];
            float4 a1 = *(const float4*)&As[kk][ty*8+4];
            float4 b4 = *(const float4*)&Bs[kk][tx*4];
            float av[8] = {a0.x,a0.y,a0.z,a0.w,a1.x,a1.y,a1.z,a1.w};
            float bv[4] = {b4.x,b4.y,b4.z,b4.w};
#pragma unroll
            for (int i = 0; i < 8; i++)
#pragma unroll
                for (int j = 0; j < 4; j++)
                    c[i][j] = fmaf(av[i], bv[j], c[i][j]);
        }
        __syncthreads();
    }
    float4 b4 = *(const float4*)(bias + bn + tx*4);
#pragma unroll
    for (int i = 0; i < 8; i++) {
        const size_t row = (size_t)(bm + ty*8 + i);
        float4 g;
        g.x = 1.f / (1.f + __expf(-(c[i][0] + b4.x)));
        g.y = 1.f / (1.f + __expf(-(c[i][1] + b4.y)));
        g.z = 1.f / (1.f + __expf(-(c[i][2] + b4.z)));
        g.w = 1.f / (1.f + __expf(-(c[i][3] + b4.w)));
        *(float4*)(G + row*256 + bn + tx*4) = g;
    }
}

// ============================================================================
__global__ __launch_bounds__(256) void finalize_kernel(
    const float* __restrict__ Or, const float* __restrict__ Oi,
    const float* __restrict__ G, float* __restrict__ out)
{
    const size_t i = ((size_t)blockIdx.x * 256 + threadIdx.x) * 4;
    float4 a = *(const float4*)(Or + i);
    float4 b = *(const float4*)(Oi + i);
    float4 g = *(const float4*)(G + i);
    float4 x, y;
    x.x = a.x*g.x; x.y = a.y*g.y; x.z = a.z*g.z; x.w = a.w*g.w;
    y.x = b.x*g.x; y.y = b.y*g.y; y.z = b.z*g.z; y.w = b.w*g.w;
    *(float4*)(out + i) = x;
    *(float4*)(out + (size_t)M_TOT * D_MOD + i) = y;
}

// ============================================================================
extern "C" void kernel_launch(void* const* d_in, const int* in_sizes, int n_in,
                              void* d_out, int out_size)
{
    const float* q_in_r  = (const float*)d_in[0];
    const float* q_in_i  = (const float*)d_in[1];
    const float* kv_in_r = (const float*)d_in[2];
    const float* kv_in_i = (const float*)d_in[3];
    const float* q_wr = (const float*)d_in[4];
    const float* q_wi = (const float*)d_in[5];
    const float* q_br = (const float*)d_in[6];
    const float* q_bi = (const float*)d_in[7];
    const float* k_wr = (const float*)d_in[8];
    const float* k_wi = (const float*)d_in[9];
    const float* k_br = (const float*)d_in[10];
    const float* k_bi = (const float*)d_in[11];
    const float* v_wr = (const float*)d_in[12];
    const float* v_wi = (const float*)d_in[13];
    const float* v_br = (const float*)d_in[14];
    const float* v_bi = (const float*)d_in[15];
    const float* o_wr = (const float*)d_in[16];
    const float* o_wi = (const float*)d_in[17];
    const float* o_br = (const float*)d_in[18];
    const float* o_bi = (const float*)d_in[19];
    const float* gate_w = (const float*)d_in[20];
    const float* gate_b = (const float*)d_in[21];

    float *p_qr, *p_qi, *p_kr, *p_ki, *p_vr, *p_vi;
    float *p_cr, *p_ci, *p_or, *p_oi, *p_g, *p_sc;
    __half *p_attn, *p_vtr, *p_vti, *p_qcat, *p_kcat;
    cudaGetSymbolAddress((void**)&p_qr, g_qr);
    cudaGetSymbolAddress((void**)&p_qi, g_qi);
    cudaGetSymbolAddress((void**)&p_kr, g_kr);
    cudaGetSymbolAddress((void**)&p_ki, g_ki);
    cudaGetSymbolAddress((void**)&p_vr, g_vr);
    cudaGetSymbolAddress((void**)&p_vi, g_vi);
    cudaGetSymbolAddress((void**)&p_cr, g_cr);
    cudaGetSymbolAddress((void**)&p_ci, g_ci);
    cudaGetSymbolAddress((void**)&p_or, g_outr);
    cudaGetSymbolAddress((void**)&p_oi, g_outi);
    cudaGetSymbolAddress((void**)&p_g,  g_gate);
    cudaGetSymbolAddress((void**)&p_sc, g_sc);
    cudaGetSymbolAddress((void**)&p_attn, g_attn);
    cudaGetSymbolAddress((void**)&p_qcat, g_qcat);
    cudaGetSymbolAddress((void**)&p_kcat, g_kcat);
    cudaGetSymbolAddress((void**)&p_vtr, g_vtr);
    cudaGetSymbolAddress((void**)&p_vti, g_vti);

    // 3-stage pipeline dynamic smem (61440 B > 48 KB default)
    cudaFuncSetAttribute(score_mma, cudaFuncAttributeMaxDynamicSharedMemorySize, 61440);
    cudaFuncSetAttribute(ctx_mma,   cudaFuncAttributeMaxDynamicSharedMemorySize, 61440);

    const dim3 tpb(256);
    const dim3 proj_grid(M_TOT / 128, D_MOD / 64);

    // Projections (fp32 SIMT)
    cgemm_nt<<<proj_grid, tpb>>>(q_in_r, q_in_i, q_wr, q_wi, q_br, q_bi, p_qr, p_qi);
    cgemm_nt<<<proj_grid, tpb>>>(kv_in_r, kv_in_i, k_wr, k_wi, k_br, k_bi, p_kr, p_ki);
    cgemm_nt<<<proj_grid, tpb>>>(kv_in_r, kv_in_i, v_wr, v_wi, v_br, v_bi, p_vr, p_vi);

    // Convert for tensor cores
    convert_split<<<16384, tpb>>>(p_qr, p_qi, p_qcat, 0);
    convert_split<<<16384, tpb>>>(p_kr, p_ki, p_kcat, 1);
    transpose_v<<<dim3(T_SEQ/32, D_MOD/32, N_BH), dim3(32, 8)>>>(p_vr, p_vi, p_vtr, p_vti);

    // Attention on mma.sync tensor cores
    score_mma<<<dim3(16, 16, N_BH), tpb, 61440>>>(p_qcat, p_kcat, p_sc);
    softmax_rows<<<(unsigned)(N_BH * T_SEQ), tpb>>>(p_sc, p_attn);
    ctx_mma<<<dim3(16, 2, 2 * N_BH), tpb, 61440>>>(p_attn, p_vtr, p_vti, p_cr, p_ci);

    // Output projection + gating (fp32 SIMT)
    cgemm_nt<<<proj_grid, tpb>>>(p_cr, p_ci, o_wr, o_wi, o_br, o_bi, p_or, p_oi);
    gate_gemm<<<proj_grid, tpb>>>(p_or, p_oi, gate_w, gate_b, p_g);
    finalize_kernel<<<(M_TOT * D_MOD) / (256 * 4), tpb>>>(p_or, p_oi, p_g, (float*)d_out);
}

// round 13
// speedup vs baseline: 2.8802x; 1.5383x over previous
#include <cuda_runtime.h>
#include <cuda_bf16.h>
#include <cuda_fp16.h>
#include <math.h>
#include <stdint.h>

#define T_SEQ 2048
#define D_MOD 256
#define N_BH  32
#define M_TOT (N_BH * T_SEQ)   /* 65536 */
#define EPS_F 1e-8f
#define KCAT  1024              /* split-fp16 concatenated K */

// ---- scratch (device globals; no runtime allocation allowed) ----
__device__ float g_qr[M_TOT * D_MOD];
__device__ float g_qi[M_TOT * D_MOD];
__device__ float g_kr[M_TOT * D_MOD];
__device__ float g_ki[M_TOT * D_MOD];
__device__ float g_vr[M_TOT * D_MOD];
__device__ float g_vi[M_TOT * D_MOD];
__device__ float g_cr[M_TOT * D_MOD];
__device__ float g_ci[M_TOT * D_MOD];
__device__ float g_outr[M_TOT * D_MOD];
__device__ float g_outi[M_TOT * D_MOD];
__device__ float g_gate[M_TOT * D_MOD];
__device__ float g_sc[(size_t)N_BH * T_SEQ * T_SEQ];          /* 512 MB fp32 scores */
__device__ __half g_attn[(size_t)N_BH * T_SEQ * T_SEQ];       /* 256 MB fp16 attn  */
__device__ __half g_qcat[(size_t)M_TOT * KCAT];               /* 128 MB split-fp16 */
__device__ __half g_kcat[(size_t)M_TOT * KCAT];               /* 128 MB split-fp16 */
__device__ __half g_acat1[(size_t)M_TOT * KCAT];              /* 128 MB q/o acat   */
__device__ __half g_acat2[(size_t)M_TOT * KCAT];              /* 128 MB kv acat    */
__device__ __half g_vtr[(size_t)N_BH * D_MOD * T_SEQ];        /* 32 MB V^T fp16    */
__device__ __half g_vti[(size_t)N_BH * D_MOD * T_SEQ];        /* 32 MB V^T fp16    */
__device__ __half g_wq[512 * KCAT];                           /* 1 MB weight cat   */
__device__ __half g_wk[512 * KCAT];
__device__ __half g_wv[512 * KCAT];
__device__ __half g_wo[512 * KCAT];

// ============================================================================
// helpers
// ============================================================================
__device__ __forceinline__ uint32_t smem_to_u32(const void* smem_ptr) {
    uint32_t addr;
    asm("{ .reg .u64 tmp; cvta.to.shared.u64 tmp, %1; cvt.u32.u64 %0, tmp; }"
        : "=r"(addr) : "l"(smem_ptr));
    return addr;
}
__device__ __forceinline__ void cp16(uint32_t smem_addr, const void* gptr) {
    asm volatile("cp.async.cg.shared.global [%0], [%1], 16;"
                 :: "r"(smem_addr), "l"(gptr) : "memory");
}
__device__ __forceinline__ void ldsm_x4(uint32_t* r, uint32_t addr) {
    asm volatile("ldmatrix.sync.aligned.m8n8.x4.shared.b16 {%0,%1,%2,%3}, [%4];"
                 : "=r"(r[0]), "=r"(r[1]), "=r"(r[2]), "=r"(r[3]) : "r"(addr));
}
__device__ __forceinline__ void ldsm_x2(uint32_t* r, uint32_t addr) {
    asm volatile("ldmatrix.sync.aligned.m8n8.x2.shared.b16 {%0,%1}, [%2];"
                 : "=r"(r[0]), "=r"(r[1]) : "r"(addr));
}
__device__ __forceinline__ void mma_f16(float* d, const uint32_t* a, const uint32_t* b) {
    asm volatile(
        "mma.sync.aligned.m16n8k16.row.col.f32.f16.f16.f32 "
        "{%0,%1,%2,%3}, {%4,%5,%6,%7}, {%8,%9}, {%0,%1,%2,%3};"
        : "+f"(d[0]), "+f"(d[1]), "+f"(d[2]), "+f"(d[3])
        : "r"(a[0]), "r"(a[1]), "r"(a[2]), "r"(a[3]), "r"(b[0]), "r"(b[1]));
}

// ============================================================================
// Core 128x128 NT tile GEMM on mma.sync fp16 (A,B K-major), fp32 accum.
// 256 threads = 8 warps in 2(m) x 4(n); warp tile 64x32; Kblk=32.
// 3-stage cp.async pipeline in dynamic smem (61440 B).
// Epilogue callback: epi(row, col, v0, v1) for (row,col)&(row,col+1).
// ============================================================================
#define SBUF_B   10240u   /* bytes per matrix per stage: 128*40*2 */
#define STAGE_B  20480u   /* bytes per stage (A+B) */

template<int KTOT, typename Epi>
__device__ __forceinline__ void gemm_mma_core(
    const uint16_t* __restrict__ Ag, const uint16_t* __restrict__ Bg, Epi epi)
{
    extern __shared__ uint16_t sh16[];
    const uint32_t base = smem_to_u32(sh16);
    const int tid = threadIdx.x;
    const int wid = tid >> 5, lane = tid & 31;
    const int wm = wid & 1, wn = wid >> 1;

    float acc[4][4][4];
#pragma unroll
    for (int i = 0; i < 4; i++)
#pragma unroll
        for (int j = 0; j < 4; j++)
#pragma unroll
            for (int v = 0; v < 4; v++) acc[i][j][v] = 0.f;

    const int c0 = tid, c1 = tid + 256;
    const int r0 = c0 >> 2, o0 = (c0 & 3) * 8;
    const int r1 = c1 >> 2, o1 = (c1 & 3) * 8;
    const uint32_t s0 = (uint32_t)((r0 * 40 + o0) * 2);
    const uint32_t s1 = (uint32_t)((r1 * 40 + o1) * 2);

    constexpr int NIT = KTOT / 32;

#define ISSUE_STAGE(stg, itk) do {                                          \
        const uint32_t sb_ = base + (uint32_t)(stg) * STAGE_B;              \
        const int k0_ = (itk) * 32;                                         \
        cp16(sb_ + s0,          Ag + (size_t)r0 * KTOT + k0_ + o0);         \
        cp16(sb_ + SBUF_B + s0, Bg + (size_t)r0 * KTOT + k0_ + o0);         \
        cp16(sb_ + s1,          Ag + (size_t)r1 * KTOT + k0_ + o1);         \
        cp16(sb_ + SBUF_B + s1, Bg + (size_t)r1 * KTOT + k0_ + o1);         \
        asm volatile("cp.async.commit_group;" ::: "memory");                \
    } while (0)

    ISSUE_STAGE(0, 0);
    if (NIT > 1) ISSUE_STAGE(1, 1);

    for (int it = 0; it < NIT; it++) {
        if (it + 2 < NIT) {
            ISSUE_STAGE((it + 2) % 3, it + 2);
            asm volatile("cp.async.wait_group 2;" ::: "memory");
        } else if (it + 1 < NIT) {
            asm volatile("cp.async.wait_group 1;" ::: "memory");
        } else {
            asm volatile("cp.async.wait_group 0;" ::: "memory");
        }
        __syncthreads();
        const uint32_t ab = base + (uint32_t)((it % 3)) * STAGE_B;
        const uint32_t bb = ab + SBUF_B;
#pragma unroll
        for (int ks = 0; ks < 32; ks += 16) {
            uint32_t af[4][4], bf[4][2];
            const int ar = lane & 15, ac = ks + ((lane >> 4) << 3);
#pragma unroll
            for (int i = 0; i < 4; i++)
                ldsm_x4(af[i], ab + (uint32_t)(((wm * 64 + i * 16 + ar) * 40 + ac) << 1));
            const int l = lane & 15;
            const int br_ = l & 7, bc = ks + ((l >> 3) << 3);
#pragma unroll
            for (int j = 0; j < 4; j++)
                ldsm_x2(bf[j], bb + (uint32_t)(((wn * 32 + j * 8 + br_) * 40 + bc) << 1));
#pragma unroll
            for (int i = 0; i < 4; i++)
#pragma unroll
                for (int j = 0; j < 4; j++)
                    mma_f16(acc[i][j], af[i], bf[j]);
        }
        __syncthreads();
    }
#undef ISSUE_STAGE

#pragma unroll
    for (int i = 0; i < 4; i++) {
        const int row = wm * 64 + i * 16 + (lane >> 2);
#pragma unroll
        for (int j = 0; j < 4; j++) {
            const int col = wn * 32 + j * 8 + (lane & 3) * 2;
            epi(row,     col, acc[i][j][0], acc[i][j][1]);
            epi(row + 8, col, acc[i][j][2], acc[i][j][3]);
        }
    }
}

// ============================================================================
// Scores: S = Qcat @ Kcat^T * 1/16, K=1024 split-fp16
// ============================================================================
__global__ __launch_bounds__(256) void score_mma(
    const __half* __restrict__ Q, const __half* __restrict__ K,
    float* __restrict__ S)
{
    const int head = blockIdx.z;
    const int bm = blockIdx.x * 128, bn = blockIdx.y * 128;
    const uint16_t* A = (const uint16_t*)(Q + ((size_t)head * T_SEQ + bm) * KCAT);
    const uint16_t* B = (const uint16_t*)(K + ((size_t)head * T_SEQ + bn) * KCAT);
    float* C = S + ((size_t)head * T_SEQ + bm) * T_SEQ + bn;
    auto epi = [&](int r, int c, float v0, float v1) {
        *(float2*)(C + (size_t)r * T_SEQ + c) = make_float2(v0 * 0.0625f, v1 * 0.0625f);
    };
    gemm_mma_core<KCAT>(A, B, epi);
}

// ============================================================================
// Context: C[r|i] = attn @ Vt^T, fp16, K=2048. grid (16, 2, 64) z=head*2+part
// ============================================================================
__global__ __launch_bounds__(256) void ctx_mma(
    const __half* __restrict__ Attn, const __half* __restrict__ Vtr,
    const __half* __restrict__ Vti,
    float* __restrict__ Cr, float* __restrict__ Ci)
{
    const int bz = blockIdx.z;
    const int head = bz >> 1, part = bz & 1;
    const int bm = blockIdx.x * 128, bn = blockIdx.y * 128;
    const uint16_t* A = (const uint16_t*)(Attn + ((size_t)head * T_SEQ + bm) * T_SEQ);
    const __half* Vt = part ? Vti : Vtr;
    const uint16_t* B = (const uint16_t*)(Vt + ((size_t)head * D_MOD + bn) * T_SEQ);
    float* Cbase = part ? Ci : Cr;
    float* C = Cbase + ((size_t)head * T_SEQ + bm) * D_MOD + bn;
    auto epi = [&](int r, int c, float v0, float v1) {
        *(float2*)(C + (size_t)r * D_MOD + c) = make_float2(v0, v1);
    };
    gemm_mma_core<T_SEQ>(A, B, epi);
}

// ============================================================================
// Complex projection on mma.sync:
// A_cat [M,1024] = [h(Ar)|l(Ar)|h(Ai)|l(Ai)], W_cat [512,1024]:
//   rows 0-255  (Cr): [h(Wr)|h(Wr)|h(-Wi)|h(-Wi)]
//   rows 256-511(Ci): [h(Wi)|h(Wi)|h(Wr) |h(Wr) ]
// => cols 0-255: Ar*Wr^T - Ai*Wi^T ; cols 256-511: Ar*Wi^T + Ai*Wr^T
// grid (512, 4); blocks with bn>=256 write Ci.
// ============================================================================
__global__ __launch_bounds__(256) void proj_mma(
    const __half* __restrict__ Acat, const __half* __restrict__ Wcat,
    const float* __restrict__ bR, const float* __restrict__ bI,
    float* __restrict__ Cr, float* __restrict__ Ci)
{
    const int bm = blockIdx.x * 128, bn = blockIdx.y * 128;
    const uint16_t* A = (const uint16_t*)(Acat + (size_t)bm * KCAT);
    const uint16_t* B = (const uint16_t*)(Wcat + (size_t)bn * KCAT);
    float* Cbase = (bn >= 256) ? Ci : Cr;
    const float* bias = (bn >= 256) ? bI : bR;
    const int coff = bn & 255;
    auto epi = [&](int r, int c, float v0, float v1) {
        const int gc = coff + c;
        *(float2*)(Cbase + (size_t)(bm + r) * D_MOD + gc)
            = make_float2(v0 + __ldg(bias + gc), v1 + __ldg(bias + gc + 1));
    };
    gemm_mma_core<KCAT>(A, B, epi);
}

// ============================================================================
// Build W_cat [512,1024] fp16 from Wr, Wi [256,256] fp32. grid 512 x 256 thr.
// ============================================================================
__device__ __forceinline__ uint32_t pack_h2(float a, float b) {
    __half2 t = __floats2half2_rn(a, b);
    return *(uint32_t*)&t;
}
__global__ __launch_bounds__(256) void convert_wcat(
    const float* __restrict__ Wr, const float* __restrict__ Wi,
    __half* __restrict__ Wcat)
{
    const int t = blockIdx.x * 256 + threadIdx.x;
    const int r = t >> 8;              /* 0..511 */
    const int c = (t & 255) * 4;       /* 0..1020 */
    const int seg = c >> 8;            /* 0..3 */
    const int k = c & 255;
    const int m = r & 255;
    const float* src;
    float sign = 1.f;
    if (r < 256) {
        if (seg < 2) src = Wr;
        else { src = Wi; sign = -1.f; }
    } else {
        src = (seg < 2) ? Wi : Wr;
    }
    float4 w = *(const float4*)(src + (size_t)m * 256 + k);
    uint32_t* out = (uint32_t*)(Wcat + (size_t)r * KCAT + c);
    out[0] = pack_h2(sign * w.x, sign * w.y);
    out[1] = pack_h2(sign * w.z, sign * w.w);
}

// ============================================================================
// Split-fp16 conversion -> row of 1024 fp16 (4 segments of 256).
// Q mode (isK=0): [hi(r) | lo(r) | hi(i) | lo(i)]   (also the proj A_cat!)
// K mode (isK=1): [hi(r) | hi(r) | hi(i) | hi(i)]
// ============================================================================
__global__ __launch_bounds__(256) void convert_split(
    const float* __restrict__ Xr, const float* __restrict__ Xi,
    __half* __restrict__ cat, int isK)
{
    const size_t t = (size_t)blockIdx.x * 256 + threadIdx.x;
    const size_t row = t >> 6;
    const int c = (int)(t & 63) << 2;
    float4 xr = *(const float4*)(Xr + row*256 + c);
    float4 xi = *(const float4*)(Xi + row*256 + c);
    float vr[4] = {xr.x, xr.y, xr.z, xr.w};
    float vi[4] = {xi.x, xi.y, xi.z, xi.w};
    float hr[4], lr[4], hi[4], li[4];
#pragma unroll
    for (int j = 0; j < 4; j++) {
        __half h = __float2half_rn(vr[j]);
        hr[j] = __half2float(h); lr[j] = vr[j] - hr[j];
        __half g = __float2half_rn(vi[j]);
        hi[j] = __half2float(g); li[j] = vi[j] - hi[j];
    }
    uint32_t* out = (uint32_t*)(cat + row * KCAT);
    const int c2 = c >> 1;
    uint32_t phr0 = pack_h2(hr[0], hr[1]), phr1 = pack_h2(hr[2], hr[3]);
    uint32_t phi0 = pack_h2(hi[0], hi[1]), phi1 = pack_h2(hi[2], hi[3]);
    if (isK) {
        out[c2]           = phr0; out[c2+1]           = phr1;
        out[128 + c2]     = phr0; out[128 + c2+1]     = phr1;
        out[256 + c2]     = phi0; out[256 + c2+1]     = phi1;
        out[384 + c2]     = phi0; out[384 + c2+1]     = phi1;
    } else {
        uint32_t plr0 = pack_h2(lr[0], lr[1]), plr1 = pack_h2(lr[2], lr[3]);
        uint32_t pli0 = pack_h2(li[0], li[1]), pli1 = pack_h2(li[2], li[3]);
        out[c2]           = phr0; out[c2+1]           = phr1;
        out[128 + c2]     = plr0; out[128 + c2+1]     = plr1;
        out[256 + c2]     = phi0; out[256 + c2+1]     = phi1;
        out[384 + c2]     = pli0; out[384 + c2+1]     = pli1;
    }
}

// ============================================================================
// Transpose V fp32 [bh][k=2048][n=256] -> fp16 [bh][n=256][k=2048]
// ============================================================================
__global__ void transpose_v(
    const float* __restrict__ Vr, const float* __restrict__ Vi,
    __half* __restrict__ Vtr, __half* __restrict__ Vti)
{
    __shared__ float tr[32][33], ti[32][33];
    const int head = blockIdx.z;
    const int k0 = blockIdx.x * 32, n0 = blockIdx.y * 32;
    const int tx = threadIdx.x, ty = threadIdx.y;
    const size_t ibase = (size_t)head * T_SEQ * 256;
#pragma unroll
    for (int i = 0; i < 32; i += 8) {
        tr[ty+i][tx] = Vr[ibase + (size_t)(k0+ty+i)*256 + n0+tx];
        ti[ty+i][tx] = Vi[ibase + (size_t)(k0+ty+i)*256 + n0+tx];
    }
    __syncthreads();
    const size_t obase = ((size_t)head * 256 + n0) * T_SEQ + k0;
#pragma unroll
    for (int i = 0; i < 32; i += 8) {
        Vtr[obase + (size_t)(ty+i)*T_SEQ + tx] = __float2half(tr[tx][ty+i]);
        Vti[obase + (size_t)(ty+i)*T_SEQ + tx] = __float2half(ti[tx][ty+i]);
    }
}

// ============================================================================
// Row softmax: read fp32 scores, write fp16 attn
// ============================================================================
__global__ __launch_bounds__(256) void softmax_rows(
    const float* __restrict__ S, __half* __restrict__ A)
{
    const float* p = S + (size_t)blockIdx.x * T_SEQ;
    __half* ap = A + (size_t)blockIdx.x * T_SEQ;
    const int tid = threadIdx.x;
    float v[8];
    float m = -3.4e38f;
#pragma unroll
    for (int r = 0; r < 8; r++) { v[r] = p[tid + (r << 8)]; m = fmaxf(m, v[r]); }
#pragma unroll
    for (int o = 16; o > 0; o >>= 1) m = fmaxf(m, __shfl_xor_sync(0xffffffffu, m, o));
    __shared__ float red[8];
    if ((tid & 31) == 0) red[tid >> 5] = m;
    __syncthreads();
    m = red[0];
#pragma unroll
    for (int w = 1; w < 8; w++) m = fmaxf(m, red[w]);
    float sum = 0.f;
#pragma unroll
    for (int r = 0; r < 8; r++) { v[r] = __expf(v[r] - m); sum += v[r]; }
#pragma unroll
    for (int o = 16; o > 0; o >>= 1) sum += __shfl_xor_sync(0xffffffffu, sum, o);
    __syncthreads();
    if ((tid & 31) == 0) red[tid >> 5] = sum;
    __syncthreads();
    sum = 0.f;
#pragma unroll
    for (int w = 0; w < 8; w++) sum += red[w];
    const float inv = 1.f / sum;
#pragma unroll
    for (int r = 0; r < 8; r++) ap[tid + (r << 8)] = __float2half(v[r] * inv);
}

// ============================================================================
// Gate GEMM: G = sigmoid( mag(Or,Oi) @ W^T + bias )  (fp32 SIMT)
// ============================================================================
__global__ __launch_bounds__(256) void gate_gemm(
    const float* __restrict__ Or, const float* __restrict__ Oi,
    const float* __restrict__ W, const float* __restrict__ bias,
    float* __restrict__ G)
{
    __shared__ float As[8][132], Bs[8][68];
    const int bm = blockIdx.x * 128, bn = blockIdx.y * 64;
    const int tid = threadIdx.x;
    const int ty = tid >> 4, tx = tid & 15;
    const int lrow = tid >> 1;
    const int lk   = (tid & 1) << 2;
    const int brow = (tid & 127) >> 1;

    float c[8][4];
#pragma unroll
    for (int i = 0; i < 8; i++)
#pragma unroll
        for (int j = 0; j < 4; j++) c[i][j] = 0.f;

    for (int k0 = 0; k0 < 256; k0 += 8) {
        float4 o1 = *(const float4*)(Or + (size_t)(bm + lrow) * 256 + k0 + lk);
        float4 o2 = *(const float4*)(Oi + (size_t)(bm + lrow) * 256 + k0 + lk);
        As[lk+0][lrow] = sqrtf(o1.x*o1.x + o2.x*o2.x + EPS_F);
        As[lk+1][lrow] = sqrtf(o1.y*o1.y + o2.y*o2.y + EPS_F);
        As[lk+2][lrow] = sqrtf(o1.z*o1.z + o2.z*o2.z + EPS_F);
        As[lk+3][lrow] = sqrtf(o1.w*o1.w + o2.w*o2.w + EPS_F);
        if (tid < 128) {
            float4 w = *(const float4*)(W + (size_t)(bn + brow) * 256 + k0 + lk);
            Bs[lk+0][brow] = w.x; Bs[lk+1][brow] = w.y;
            Bs[lk+2][brow] = w.z; Bs[lk+3][brow] = w.w;
        }
        __syncthreads();
#pragma unroll
        for (int kk = 0; kk < 8; kk++) {
            float4 a0 = *(const float4*)&As[kk][ty*8];
            float4 a1 = *(const float4*)&As[kk][ty*8+4];
            float4 b4 = *(const float4*)&Bs[kk][tx*4];
            float av[8] = {a0.x,a0.y,a0.z,a0.w,a1.x,a1.y,a1.z,a1.w};
            float bv[4] = {b4.x,b4.y,b4.z,b4.w};
#pragma unroll
            for (int i = 0; i < 8; i++)
#pragma unroll
                for (int j = 0; j < 4; j++)
                    c[i][j] = fmaf(av[i], bv[j], c[i][j]);
        }
        __syncthreads();
    }
    float4 b4 = *(const float4*)(bias + bn + tx*4);
#pragma unroll
    for (int i = 0; i < 8; i++) {
        const size_t row = (size_t)(bm + ty*8 + i);
        float4 g;
        g.x = 1.f / (1.f + __expf(-(c[i][0] + b4.x)));
        g.y = 1.f / (1.f + __expf(-(c[i][1] + b4.y)));
        g.z = 1.f / (1.f + __expf(-(c[i][2] + b4.z)));
        g.w = 1.f / (1.f + __expf(-(c[i][3] + b4.w)));
        *(float4*)(G + row*256 + bn + tx*4) = g;
    }
}

// ============================================================================
__global__ __launch_bounds__(256) void finalize_kernel(
    const float* __restrict__ Or, const float* __restrict__ Oi,
    const float* __restrict__ G, float* __restrict__ out)
{
    const size_t i = ((size_t)blockIdx.x * 256 + threadIdx.x) * 4;
    float4 a = *(const float4*)(Or + i);
    float4 b = *(const float4*)(Oi + i);
    float4 g = *(const float4*)(G + i);
    float4 x, y;
    x.x = a.x*g.x; x.y = a.y*g.y; x.z = a.z*g.z; x.w = a.w*g.w;
    y.x = b.x*g.x; y.y = b.y*g.y; y.z = b.z*g.z; y.w = b.w*g.w;
    *(float4*)(out + i) = x;
    *(float4*)(out + (size_t)M_TOT * D_MOD + i) = y;
}

// ============================================================================
extern "C" void kernel_launch(void* const* d_in, const int* in_sizes, int n_in,
                              void* d_out, int out_size)
{
    const float* q_in_r  = (const float*)d_in[0];
    const float* q_in_i  = (const float*)d_in[1];
    const float* kv_in_r = (const float*)d_in[2];
    const float* kv_in_i = (const float*)d_in[3];
    const float* q_wr = (const float*)d_in[4];
    const float* q_wi = (const float*)d_in[5];
    const float* q_br = (const float*)d_in[6];
    const float* q_bi = (const float*)d_in[7];
    const float* k_wr = (const float*)d_in[8];
    const float* k_wi = (const float*)d_in[9];
    const float* k_br = (const float*)d_in[10];
    const float* k_bi = (const float*)d_in[11];
    const float* v_wr = (const float*)d_in[12];
    const float* v_wi = (const float*)d_in[13];
    const float* v_br = (const float*)d_in[14];
    const float* v_bi = (const float*)d_in[15];
    const float* o_wr = (const float*)d_in[16];
    const float* o_wi = (const float*)d_in[17];
    const float* o_br = (const float*)d_in[18];
    const float* o_bi = (const float*)d_in[19];
    const float* gate_w = (const float*)d_in[20];
    const float* gate_b = (const float*)d_in[21];

    float *p_qr, *p_qi, *p_kr, *p_ki, *p_vr, *p_vi;
    float *p_cr, *p_ci, *p_or, *p_oi, *p_g, *p_sc;
    __half *p_attn, *p_vtr, *p_vti, *p_qcat, *p_kcat, *p_acat1, *p_acat2;
    __half *p_wq, *p_wk, *p_wv, *p_wo;
    cudaGetSymbolAddress((void**)&p_qr, g_qr);
    cudaGetSymbolAddress((void**)&p_qi, g_qi);
    cudaGetSymbolAddress((void**)&p_kr, g_kr);
    cudaGetSymbolAddress((void**)&p_ki, g_ki);
    cudaGetSymbolAddress((void**)&p_vr, g_vr);
    cudaGetSymbolAddress((void**)&p_vi, g_vi);
    cudaGetSymbolAddress((void**)&p_cr, g_cr);
    cudaGetSymbolAddress((void**)&p_ci, g_ci);
    cudaGetSymbolAddress((void**)&p_or, g_outr);
    cudaGetSymbolAddress((void**)&p_oi, g_outi);
    cudaGetSymbolAddress((void**)&p_g,  g_gate);
    cudaGetSymbolAddress((void**)&p_sc, g_sc);
    cudaGetSymbolAddress((void**)&p_attn, g_attn);
    cudaGetSymbolAddress((void**)&p_qcat, g_qcat);
    cudaGetSymbolAddress((void**)&p_kcat, g_kcat);
    cudaGetSymbolAddress((void**)&p_acat1, g_acat1);
    cudaGetSymbolAddress((void**)&p_acat2, g_acat2);
    cudaGetSymbolAddress((void**)&p_vtr, g_vtr);
    cudaGetSymbolAddress((void**)&p_vti, g_vti);
    cudaGetSymbolAddress((void**)&p_wq, g_wq);
    cudaGetSymbolAddress((void**)&p_wk, g_wk);
    cudaGetSymbolAddress((void**)&p_wv, g_wv);
    cudaGetSymbolAddress((void**)&p_wo, g_wo);

    cudaFuncSetAttribute(score_mma, cudaFuncAttributeMaxDynamicSharedMemorySize, 61440);
    cudaFuncSetAttribute(ctx_mma,   cudaFuncAttributeMaxDynamicSharedMemorySize, 61440);
    cudaFuncSetAttribute(proj_mma,  cudaFuncAttributeMaxDynamicSharedMemorySize, 61440);

    const dim3 tpb(256);
    const dim3 proj_grid(M_TOT / 128, 4);

    // Build split-fp16 A operands for projections + weight cats
    convert_split<<<16384, tpb>>>(q_in_r, q_in_i, p_acat1, 0);
    convert_split<<<16384, tpb>>>(kv_in_r, kv_in_i, p_acat2, 0);
    convert_wcat<<<512, tpb>>>(q_wr, q_wi, p_wq);
    convert_wcat<<<512, tpb>>>(k_wr, k_wi, p_wk);
    convert_wcat<<<512, tpb>>>(v_wr, v_wi, p_wv);
    convert_wcat<<<512, tpb>>>(o_wr, o_wi, p_wo);

    // Projections on tensor cores (split-fp16)
    proj_mma<<<proj_grid, tpb, 61440>>>(p_acat1, p_wq, q_br, q_bi, p_qr, p_qi);
    proj_mma<<<proj_grid, tpb, 61440>>>(p_acat2, p_wk, k_br, k_bi, p_kr, p_ki);
    proj_mma<<<proj_grid, tpb, 61440>>>(p_acat2, p_wv, v_br, v_bi, p_vr, p_vi);

    // Convert for attention
    convert_split<<<16384, tpb>>>(p_qr, p_qi, p_qcat, 0);
    convert_split<<<16384, tpb>>>(p_kr, p_ki, p_kcat, 1);
    transpose_v<<<dim3(T_SEQ/32, D_MOD/32, N_BH), dim3(32, 8)>>>(p_vr, p_vi, p_vtr, p_vti);

    // Attention on mma.sync tensor cores
    score_mma<<<dim3(16, 16, N_BH), tpb, 61440>>>(p_qcat, p_kcat, p_sc);
    softmax_rows<<<(unsigned)(N_BH * T_SEQ), tpb>>>(p_sc, p_attn);
    ctx_mma<<<dim3(16, 2, 2 * N_BH), tpb, 61440>>>(p_attn, p_vtr, p_vti, p_cr, p_ci);

    // Output projection (tensor cores) + gating
    convert_split<<<16384, tpb>>>(p_cr, p_ci, p_acat1, 0);
    proj_mma<<<proj_grid, tpb, 61440>>>(p_acat1, p_wo, o_br, o_bi, p_or, p_oi);
    gate_gemm<<<dim3(M_TOT / 128, D_MOD / 64), tpb>>>(p_or, p_oi, gate_w, gate_b, p_g);
    finalize_kernel<<<(M_TOT * D_MOD) / (256 * 4), tpb>>>(p_or, p_oi, p_g, (float*)d_out);
}

// round 14
// speedup vs baseline: 3.7547x; 1.3036x over previous
#include <cuda_runtime.h>
#include <cuda_bf16.h>
#include <cuda_fp16.h>
#include <math.h>
#include <stdint.h>

#define T_SEQ 2048
#define D_MOD 256
#define N_BH  32
#define M_TOT (N_BH * T_SEQ)   /* 65536 */
#define EPS_F 1e-8f
#define KCAT  1024              /* split-fp16 K for projections */
#define KSC   512               /* fp16 K for scores / gate */

// ---- scratch (device globals; no runtime allocation allowed) ----
__device__ float g_outr[M_TOT * D_MOD];
__device__ float g_outi[M_TOT * D_MOD];
__device__ float g_sc[(size_t)N_BH * T_SEQ * T_SEQ];          /* 512 MB fp32 scores */
__device__ __half g_attn[(size_t)N_BH * T_SEQ * T_SEQ];       /* 256 MB fp16 attn  */
__device__ __half g_qcat[(size_t)M_TOT * KSC];                /* 64 MB  [hr|hi] / magcat */
__device__ __half g_kcat[(size_t)M_TOT * KSC];                /* 64 MB  [hr|hi]    */
__device__ __half g_vcat[(size_t)M_TOT * KSC];                /* 64 MB  [hr|hi]    */
__device__ __half g_acat1[(size_t)M_TOT * KCAT];              /* 128 MB q input acat */
__device__ __half g_acat2[(size_t)M_TOT * KCAT];              /* 128 MB kv acat / ctx acat */
__device__ __half g_vtr[(size_t)N_BH * D_MOD * T_SEQ];        /* 32 MB V^T fp16    */
__device__ __half g_vti[(size_t)N_BH * D_MOD * T_SEQ];        /* 32 MB V^T fp16    */
__device__ __half g_wq[512 * KCAT];                           /* 1 MB weight cat   */
__device__ __half g_wk[512 * KCAT];
__device__ __half g_wv[512 * KCAT];
__device__ __half g_wo[512 * KCAT];
__device__ __half g_wg[256 * KSC];                            /* gate W cat        */

// ============================================================================
// helpers
// ============================================================================
__device__ __forceinline__ uint32_t smem_to_u32(const void* smem_ptr) {
    uint32_t addr;
    asm("{ .reg .u64 tmp; cvta.to.shared.u64 tmp, %1; cvt.u32.u64 %0, tmp; }"
        : "=r"(addr) : "l"(smem_ptr));
    return addr;
}
__device__ __forceinline__ void cp16(uint32_t smem_addr, const void* gptr) {
    asm volatile("cp.async.cg.shared.global [%0], [%1], 16;"
                 :: "r"(smem_addr), "l"(gptr) : "memory");
}
__device__ __forceinline__ void ldsm_x4(uint32_t* r, uint32_t addr) {
    asm volatile("ldmatrix.sync.aligned.m8n8.x4.shared.b16 {%0,%1,%2,%3}, [%4];"
                 : "=r"(r[0]), "=r"(r[1]), "=r"(r[2]), "=r"(r[3]) : "r"(addr));
}
__device__ __forceinline__ void ldsm_x2(uint32_t* r, uint32_t addr) {
    asm volatile("ldmatrix.sync.aligned.m8n8.x2.shared.b16 {%0,%1}, [%2];"
                 : "=r"(r[0]), "=r"(r[1]) : "r"(addr));
}
__device__ __forceinline__ void mma_f16(float* d, const uint32_t* a, const uint32_t* b) {
    asm volatile(
        "mma.sync.aligned.m16n8k16.row.col.f32.f16.f16.f32 "
        "{%0,%1,%2,%3}, {%4,%5,%6,%7}, {%8,%9}, {%0,%1,%2,%3};"
        : "+f"(d[0]), "+f"(d[1]), "+f"(d[2]), "+f"(d[3])
        : "r"(a[0]), "r"(a[1]), "r"(a[2]), "r"(a[3]), "r"(b[0]), "r"(b[1]));
}
__device__ __forceinline__ uint32_t pack_h2(float a, float b) {
    __half2 t = __floats2half2_rn(a, b);
    return *(uint32_t*)&t;
}

// ============================================================================
// Core 128x128 NT tile GEMM on mma.sync fp16 (A,B K-major), fp32 accum.
// 256 threads = 8 warps in 2(m) x 4(n); warp tile 64x32; Kblk=32.
// 3-stage cp.async pipeline in dynamic smem (61440 B).
// Epilogue callback: epi(row, col, v0, v1).
// ============================================================================
#define SBUF_B   10240u
#define STAGE_B  20480u

template<int KTOT, typename Epi>
__device__ __forceinline__ void gemm_mma_core(
    const uint16_t* __restrict__ Ag, const uint16_t* __restrict__ Bg, Epi epi)
{
    extern __shared__ uint16_t sh16[];
    const uint32_t base = smem_to_u32(sh16);
    const int tid = threadIdx.x;
    const int wid = tid >> 5, lane = tid & 31;
    const int wm = wid & 1, wn = wid >> 1;

    float acc[4][4][4];
#pragma unroll
    for (int i = 0; i < 4; i++)
#pragma unroll
        for (int j = 0; j < 4; j++)
#pragma unroll
            for (int v = 0; v < 4; v++) acc[i][j][v] = 0.f;

    const int c0 = tid, c1 = tid + 256;
    const int r0 = c0 >> 2, o0 = (c0 & 3) * 8;
    const int r1 = c1 >> 2, o1 = (c1 & 3) * 8;
    const uint32_t s0 = (uint32_t)((r0 * 40 + o0) * 2);
    const uint32_t s1 = (uint32_t)((r1 * 40 + o1) * 2);

    constexpr int NIT = KTOT / 32;

#define ISSUE_STAGE(stg, itk) do {                                          \
        const uint32_t sb_ = base + (uint32_t)(stg) * STAGE_B;              \
        const int k0_ = (itk) * 32;                                         \
        cp16(sb_ + s0,          Ag + (size_t)r0 * KTOT + k0_ + o0);         \
        cp16(sb_ + SBUF_B + s0, Bg + (size_t)r0 * KTOT + k0_ + o0);         \
        cp16(sb_ + s1,          Ag + (size_t)r1 * KTOT + k0_ + o1);         \
        cp16(sb_ + SBUF_B + s1, Bg + (size_t)r1 * KTOT + k0_ + o1);         \
        asm volatile("cp.async.commit_group;" ::: "memory");                \
    } while (0)

    ISSUE_STAGE(0, 0);
    if (NIT > 1) ISSUE_STAGE(1, 1);

    for (int it = 0; it < NIT; it++) {
        if (it + 2 < NIT) {
            ISSUE_STAGE((it + 2) % 3, it + 2);
            asm volatile("cp.async.wait_group 2;" ::: "memory");
        } else if (it + 1 < NIT) {
            asm volatile("cp.async.wait_group 1;" ::: "memory");
        } else {
            asm volatile("cp.async.wait_group 0;" ::: "memory");
        }
        __syncthreads();
        const uint32_t ab = base + (uint32_t)((it % 3)) * STAGE_B;
        const uint32_t bb = ab + SBUF_B;
#pragma unroll
        for (int ks = 0; ks < 32; ks += 16) {
            uint32_t af[4][4], bf[4][2];
            const int ar = lane & 15, ac = ks + ((lane >> 4) << 3);
#pragma unroll
            for (int i = 0; i < 4; i++)
                ldsm_x4(af[i], ab + (uint32_t)(((wm * 64 + i * 16 + ar) * 40 + ac) << 1));
            const int l = lane & 15;
            const int br_ = l & 7, bc = ks + ((l >> 3) << 3);
#pragma unroll
            for (int j = 0; j < 4; j++)
                ldsm_x2(bf[j], bb + (uint32_t)(((wn * 32 + j * 8 + br_) * 40 + bc) << 1));
#pragma unroll
            for (int i = 0; i < 4; i++)
#pragma unroll
                for (int j = 0; j < 4; j++)
                    mma_f16(acc[i][j], af[i], bf[j]);
        }
        __syncthreads();
    }
#undef ISSUE_STAGE

#pragma unroll
    for (int i = 0; i < 4; i++) {
        const int row = wm * 64 + i * 16 + (lane >> 2);
#pragma unroll
        for (int j = 0; j < 4; j++) {
            const int col = wn * 32 + j * 8 + (lane & 3) * 2;
            epi(row,     col, acc[i][j][0], acc[i][j][1]);
            epi(row + 8, col, acc[i][j][2], acc[i][j][3]);
        }
    }
}

// ============================================================================
// Scores: S = Qcat @ Kcat^T * 1/16, K=512 fp16 ([hr|hi] both sides)
// ============================================================================
__global__ __launch_bounds__(256) void score_mma(
    const __half* __restrict__ Q, const __half* __restrict__ K,
    float* __restrict__ S)
{
    const int head = blockIdx.z;
    const int bm = blockIdx.x * 128, bn = blockIdx.y * 128;
    const uint16_t* A = (const uint16_t*)(Q + ((size_t)head * T_SEQ + bm) * KSC);
    const uint16_t* B = (const uint16_t*)(K + ((size_t)head * T_SEQ + bn) * KSC);
    float* C = S + ((size_t)head * T_SEQ + bm) * T_SEQ + bn;
    auto epi = [&](int r, int c, float v0, float v1) {
        *(float2*)(C + (size_t)r * T_SEQ + c) = make_float2(v0 * 0.0625f, v1 * 0.0625f);
    };
    gemm_mma_core<KSC>(A, B, epi);
}

// ============================================================================
// Context: attn @ Vt^T, fp16, K=2048. grid (16, 2, 64) z=head*2+part.
// Epilogue writes h/l split DIRECTLY into acat [M,1024]:
//   part=0 (real): h at +c, l at +256+c ; part=1 (imag): h at +512+c, l at +768+c
// ============================================================================
__global__ __launch_bounds__(256) void ctx_mma(
    const __half* __restrict__ Attn, const __half* __restrict__ Vtr,
    const __half* __restrict__ Vti, __half* __restrict__ Acat)
{
    const int bz = blockIdx.z;
    const int head = bz >> 1, part = bz & 1;
    const int bm = blockIdx.x * 128, bn = blockIdx.y * 128;
    const uint16_t* A = (const uint16_t*)(Attn + ((size_t)head * T_SEQ + bm) * T_SEQ);
    const __half* Vt = part ? Vti : Vtr;
    const uint16_t* B = (const uint16_t*)(Vt + ((size_t)head * D_MOD + bn) * T_SEQ);
    const size_t rbase = (size_t)head * T_SEQ + bm;
    const int hoff = part * 512;
    auto epi = [&](int r, int c, float v0, float v1) {
        uint32_t* out = (uint32_t*)(Acat + (rbase + r) * KCAT);
        float h0f = __half2float(__float2half_rn(v0));
        float h1f = __half2float(__float2half_rn(v1));
        const int gc = bn + c;
        out[(hoff + gc) >> 1]       = pack_h2(h0f, h1f);
        out[(hoff + 256 + gc) >> 1] = pack_h2(v0 - h0f, v1 - h1f);
    };
    gemm_mma_core<T_SEQ>(A, B, epi);
}

// ============================================================================
// Projection (fp16-cat output, for q/k/v):
// A_cat [M,1024] = [h(Ar)|l(Ar)|h(Ai)|l(Ai)], W_cat [512,1024] (see convert_wcat).
// Epilogue: +bias, convert to fp16, write cat[row*512 + (i?256:0) + col].
// grid (M/128, 4).
// ============================================================================
__global__ __launch_bounds__(256) void proj_h16(
    const __half* __restrict__ Acat, const __half* __restrict__ Wcat,
    const float* __restrict__ bR, const float* __restrict__ bI,
    __half* __restrict__ Cat)
{
    const int bm = blockIdx.x * 128, bn = blockIdx.y * 128;
    const uint16_t* A = (const uint16_t*)(Acat + (size_t)bm * KCAT);
    const uint16_t* B = (const uint16_t*)(Wcat + (size_t)bn * KCAT);
    const float* bias = (bn >= 256) ? bI : bR;
    const int off = (bn >= 256) ? 256 + (bn & 255) : bn;
    auto epi = [&](int r, int c, float v0, float v1) {
        const int gc = (bn & 255) + c;
        *(uint32_t*)(Cat + (size_t)(bm + r) * KSC + off + c)
            = pack_h2(v0 + __ldg(bias + gc), v1 + __ldg(bias + gc + 1));
    };
    gemm_mma_core<KCAT>(A, B, epi);
}

// ============================================================================
// Projection (fp32 output, for o): +bias, write Cr/Ci. grid (M/128, 4).
// ============================================================================
__global__ __launch_bounds__(256) void proj_mma(
    const __half* __restrict__ Acat, const __half* __restrict__ Wcat,
    const float* __restrict__ bR, const float* __restrict__ bI,
    float* __restrict__ Cr, float* __restrict__ Ci)
{
    const int bm = blockIdx.x * 128, bn = blockIdx.y * 128;
    const uint16_t* A = (const uint16_t*)(Acat + (size_t)bm * KCAT);
    const uint16_t* B = (const uint16_t*)(Wcat + (size_t)bn * KCAT);
    float* Cbase = (bn >= 256) ? Ci : Cr;
    const float* bias = (bn >= 256) ? bI : bR;
    const int coff = bn & 255;
    auto epi = [&](int r, int c, float v0, float v1) {
        const int gc = coff + c;
        *(float2*)(Cbase + (size_t)(bm + r) * D_MOD + gc)
            = make_float2(v0 + __ldg(bias + gc), v1 + __ldg(bias + gc + 1));
    };
    gemm_mma_core<KCAT>(A, B, epi);
}

// ============================================================================
// Gate + finalize fused: G = sigmoid(magcat @ Wg^T + b); out = (Or*G, Oi*G)
// magcat [M,512] = [h(mag)|l(mag)], Wg [256,512]. grid (M/128, 2).
// ============================================================================
__global__ __launch_bounds__(256) void gate_mma(
    const __half* __restrict__ Mag, const __half* __restrict__ Wg,
    const float* __restrict__ bias,
    const float* __restrict__ Or, const float* __restrict__ Oi,
    float* __restrict__ out)
{
    const int bm = blockIdx.x * 128, bn = blockIdx.y * 128;
    const uint16_t* A = (const uint16_t*)(Mag + (size_t)bm * KSC);
    const uint16_t* B = (const uint16_t*)(Wg + (size_t)bn * KSC);
    auto epi = [&](int r, int c, float v0, float v1) {
        const int gc = bn + c;
        const size_t row = (size_t)(bm + r);
        float g0 = 1.f / (1.f + __expf(-(v0 + __ldg(bias + gc))));
        float g1 = 1.f / (1.f + __expf(-(v1 + __ldg(bias + gc + 1))));
        float2 a = *(const float2*)(Or + row * D_MOD + gc);
        float2 b = *(const float2*)(Oi + row * D_MOD + gc);
        *(float2*)(out + row * D_MOD + gc) = make_float2(a.x * g0, a.y * g1);
        *(float2*)(out + (size_t)M_TOT * D_MOD + row * D_MOD + gc)
            = make_float2(b.x * g0, b.y * g1);
    };
    gemm_mma_core<KSC>(A, B, epi);
}

// ============================================================================
// Build W_cat [512,1024] fp16 from Wr, Wi [256,256] fp32. grid 512 x 256 thr.
//   rows 0-255  (Cr): [h(Wr)|h(Wr)|h(-Wi)|h(-Wi)]
//   rows 256-511(Ci): [h(Wi)|h(Wi)|h(Wr) |h(Wr) ]
// ============================================================================
__global__ __launch_bounds__(256) void convert_wcat(
    const float* __restrict__ Wr, const float* __restrict__ Wi,
    __half* __restrict__ Wcat)
{
    const int t = blockIdx.x * 256 + threadIdx.x;
    const int r = t >> 8;
    const int c = (t & 255) * 4;
    const int seg = c >> 8;
    const int k = c & 255;
    const int m = r & 255;
    const float* src;
    float sign = 1.f;
    if (r < 256) {
        if (seg < 2) src = Wr;
        else { src = Wi; sign = -1.f; }
    } else {
        src = (seg < 2) ? Wi : Wr;
    }
    float4 w = *(const float4*)(src + (size_t)m * 256 + k);
    uint32_t* out = (uint32_t*)(Wcat + (size_t)r * KCAT + c);
    out[0] = pack_h2(sign * w.x, sign * w.y);
    out[1] = pack_h2(sign * w.z, sign * w.w);
}

// Gate weight cat [256,512] = [h(W)|h(W)]. 128 blocks x 256 thr.
__global__ __launch_bounds__(256) void convert_wgate(
    const float* __restrict__ W, __half* __restrict__ Wg)
{
    const int t = blockIdx.x * 256 + threadIdx.x;
    const int r = t >> 7;
    const int c = (t & 127) * 4;
    const int k = c & 255;
    float4 w = *(const float4*)(W + (size_t)r * 256 + k);
    uint32_t* out = (uint32_t*)(Wg + (size_t)r * KSC + c);
    out[0] = pack_h2(w.x, w.y);
    out[1] = pack_h2(w.z, w.w);
}

// ============================================================================
// Input split-fp16 conversion -> row of 1024 fp16 [h(r)|l(r)|h(i)|l(i)].
// ============================================================================
__global__ __launch_bounds__(256) void convert_split(
    const float* __restrict__ Xr, const float* __restrict__ Xi,
    __half* __restrict__ cat)
{
    const size_t t = (size_t)blockIdx.x * 256 + threadIdx.x;
    const size_t row = t >> 6;
    const int c = (int)(t & 63) << 2;
    float4 xr = *(const float4*)(Xr + row*256 + c);
    float4 xi = *(const float4*)(Xi + row*256 + c);
    float vr[4] = {xr.x, xr.y, xr.z, xr.w};
    float vi[4] = {xi.x, xi.y, xi.z, xi.w};
    float hr[4], lr[4], hi[4], li[4];
#pragma unroll
    for (int j = 0; j < 4; j++) {
        __half h = __float2half_rn(vr[j]);
        hr[j] = __half2float(h); lr[j] = vr[j] - hr[j];
        __half g = __float2half_rn(vi[j]);
        hi[j] = __half2float(g); li[j] = vi[j] - hi[j];
    }
    uint32_t* out = (uint32_t*)(cat + row * KCAT);
    const int c2 = c >> 1;
    out[c2]         = pack_h2(hr[0], hr[1]); out[c2+1]       = pack_h2(hr[2], hr[3]);
    out[128 + c2]   = pack_h2(lr[0], lr[1]); out[128 + c2+1] = pack_h2(lr[2], lr[3]);
    out[256 + c2]   = pack_h2(hi[0], hi[1]); out[256 + c2+1] = pack_h2(hi[2], hi[3]);
    out[384 + c2]   = pack_h2(li[0], li[1]); out[384 + c2+1] = pack_h2(li[2], li[3]);
}

// ============================================================================
// Mag split: outr/outi fp32 -> magcat [M,512] = [h(mag)|l(mag)]
// ============================================================================
__global__ __launch_bounds__(256) void convert_mag(
    const float* __restrict__ Or, const float* __restrict__ Oi,
    __half* __restrict__ Mag)
{
    const size_t t = (size_t)blockIdx.x * 256 + threadIdx.x;
    const size_t row = t >> 6;
    const int c = (int)(t & 63) << 2;
    float4 a = *(const float4*)(Or + row*256 + c);
    float4 b = *(const float4*)(Oi + row*256 + c);
    float m[4] = {sqrtf(a.x*a.x + b.x*b.x + EPS_F), sqrtf(a.y*a.y + b.y*b.y + EPS_F),
                  sqrtf(a.z*a.z + b.z*b.z + EPS_F), sqrtf(a.w*a.w + b.w*b.w + EPS_F)};
    float h[4], l[4];
#pragma unroll
    for (int j = 0; j < 4; j++) {
        __half hh = __float2half_rn(m[j]);
        h[j] = __half2float(hh); l[j] = m[j] - h[j];
    }
    uint32_t* out = (uint32_t*)(Mag + row * KSC);
    const int c2 = c >> 1;
    out[c2]         = pack_h2(h[0], h[1]); out[c2+1]       = pack_h2(h[2], h[3]);
    out[128 + c2]   = pack_h2(l[0], l[1]); out[128 + c2+1] = pack_h2(l[2], l[3]);
}

// ============================================================================
// Transpose V: vcat fp16 [bh*T_SEQ][512]([hr|hi]) -> Vt[bh][n=256][k=2048] fp16
// ============================================================================
__global__ void transpose_v(
    const __half* __restrict__ Vcat,
    __half* __restrict__ Vtr, __half* __restrict__ Vti)
{
    __shared__ __half tr[32][33], ti[32][33];
    const int head = blockIdx.z;
    const int k0 = blockIdx.x * 32, n0 = blockIdx.y * 32;
    const int tx = threadIdx.x, ty = threadIdx.y;
    const size_t ibase = (size_t)head * T_SEQ;
#pragma unroll
    for (int i = 0; i < 32; i += 8) {
        const __half* src = Vcat + (ibase + k0 + ty + i) * KSC;
        tr[ty+i][tx] = src[n0 + tx];
        ti[ty+i][tx] = src[256 + n0 + tx];
    }
    __syncthreads();
    const size_t obase = ((size_t)head * 256 + n0) * T_SEQ + k0;
#pragma unroll
    for (int i = 0; i < 32; i += 8) {
        Vtr[obase + (size_t)(ty+i)*T_SEQ + tx] = tr[tx][ty+i];
        Vti[obase + (size_t)(ty+i)*T_SEQ + tx] = ti[tx][ty+i];
    }
}

// ============================================================================
// Row softmax: read fp32 scores, write fp16 attn
// ============================================================================
__global__ __launch_bounds__(256) void softmax_rows(
    const float* __restrict__ S, __half* __restrict__ A)
{
    const float* p = S + (size_t)blockIdx.x * T_SEQ;
    __half* ap = A + (size_t)blockIdx.x * T_SEQ;
    const int tid = threadIdx.x;
    float v[8];
    float m = -3.4e38f;
#pragma unroll
    for (int r = 0; r < 8; r++) { v[r] = p[tid + (r << 8)]; m = fmaxf(m, v[r]); }
#pragma unroll
    for (int o = 16; o > 0; o >>= 1) m = fmaxf(m, __shfl_xor_sync(0xffffffffu, m, o));
    __shared__ float red[8];
    if ((tid & 31) == 0) red[tid >> 5] = m;
    __syncthreads();
    m = red[0];
#pragma unroll
    for (int w = 1; w < 8; w++) m = fmaxf(m, red[w]);
    float sum = 0.f;
#pragma unroll
    for (int r = 0; r < 8; r++) { v[r] = __expf(v[r] - m); sum += v[r]; }
#pragma unroll
    for (int o = 16; o > 0; o >>= 1) sum += __shfl_xor_sync(0xffffffffu, sum, o);
    __syncthreads();
    if ((tid & 31) == 0) red[tid >> 5] = sum;
    __syncthreads();
    sum = 0.f;
#pragma unroll
    for (int w = 0; w < 8; w++) sum += red[w];
    const float inv = 1.f / sum;
#pragma unroll
    for (int r = 0; r < 8; r++) ap[tid + (r << 8)] = __float2half(v[r] * inv);
}

// ============================================================================
extern "C" void kernel_launch(void* const* d_in, const int* in_sizes, int n_in,
                              void* d_out, int out_size)
{
    const float* q_in_r  = (const float*)d_in[0];
    const float* q_in_i  = (const float*)d_in[1];
    const float* kv_in_r = (const float*)d_in[2];
    const float* kv_in_i = (const float*)d_in[3];
    const float* q_wr = (const float*)d_in[4];
    const float* q_wi = (const float*)d_in[5];
    const float* q_br = (const float*)d_in[6];
    const float* q_bi = (const float*)d_in[7];
    const float* k_wr = (const float*)d_in[8];
    const float* k_wi = (const float*)d_in[9];
    const float* k_br = (const float*)d_in[10];
    const float* k_bi = (const float*)d_in[11];
    const float* v_wr = (const float*)d_in[12];
    const float* v_wi = (const float*)d_in[13];
    const float* v_br = (const float*)d_in[14];
    const float* v_bi = (const float*)d_in[15];
    const float* o_wr = (const float*)d_in[16];
    const float* o_wi = (const float*)d_in[17];
    const float* o_br = (const float*)d_in[18];
    const float* o_bi = (const float*)d_in[19];
    const float* gate_w = (const float*)d_in[20];
    const float* gate_b = (const float*)d_in[21];

    float *p_or, *p_oi, *p_sc;
    __half *p_attn, *p_vtr, *p_vti, *p_qcat, *p_kcat, *p_vcat, *p_acat1, *p_acat2;
    __half *p_wq, *p_wk, *p_wv, *p_wo, *p_wg;
    cudaGetSymbolAddress((void**)&p_or, g_outr);
    cudaGetSymbolAddress((void**)&p_oi, g_outi);
    cudaGetSymbolAddress((void**)&p_sc, g_sc);
    cudaGetSymbolAddress((void**)&p_attn, g_attn);
    cudaGetSymbolAddress((void**)&p_qcat, g_qcat);
    cudaGetSymbolAddress((void**)&p_kcat, g_kcat);
    cudaGetSymbolAddress((void**)&p_vcat, g_vcat);
    cudaGetSymbolAddress((void**)&p_acat1, g_acat1);
    cudaGetSymbolAddress((void**)&p_acat2, g_acat2);
    cudaGetSymbolAddress((void**)&p_vtr, g_vtr);
    cudaGetSymbolAddress((void**)&p_vti, g_vti);
    cudaGetSymbolAddress((void**)&p_wq, g_wq);
    cudaGetSymbolAddress((void**)&p_wk, g_wk);
    cudaGetSymbolAddress((void**)&p_wv, g_wv);
    cudaGetSymbolAddress((void**)&p_wo, g_wo);
    cudaGetSymbolAddress((void**)&p_wg, g_wg);

    cudaFuncSetAttribute(score_mma, cudaFuncAttributeMaxDynamicSharedMemorySize, 61440);
    cudaFuncSetAttribute(ctx_mma,   cudaFuncAttributeMaxDynamicSharedMemorySize, 61440);
    cudaFuncSetAttribute(proj_mma,  cudaFuncAttributeMaxDynamicSharedMemorySize, 61440);
    cudaFuncSetAttribute(proj_h16,  cudaFuncAttributeMaxDynamicSharedMemorySize, 61440);
    cudaFuncSetAttribute(gate_mma,  cudaFuncAttributeMaxDynamicSharedMemorySize, 61440);

    const dim3 tpb(256);
    const dim3 proj_grid(M_TOT / 128, 4);

    // Input acats + weight cats
    convert_split<<<16384, tpb>>>(q_in_r, q_in_i, p_acat1);
    convert_split<<<16384, tpb>>>(kv_in_r, kv_in_i, p_acat2);
    convert_wcat<<<512, tpb>>>(q_wr, q_wi, p_wq);
    convert_wcat<<<512, tpb>>>(k_wr, k_wi, p_wk);
    convert_wcat<<<512, tpb>>>(v_wr, v_wi, p_wv);
    convert_wcat<<<512, tpb>>>(o_wr, o_wi, p_wo);
    convert_wgate<<<128, tpb>>>(gate_w, p_wg);

    // q/k/v projections -> fp16 cats directly
    proj_h16<<<proj_grid, tpb, 61440>>>(p_acat1, p_wq, q_br, q_bi, p_qcat);
    proj_h16<<<proj_grid, tpb, 61440>>>(p_acat2, p_wk, k_br, k_bi, p_kcat);
    proj_h16<<<proj_grid, tpb, 61440>>>(p_acat2, p_wv, v_br, v_bi, p_vcat);
    transpose_v<<<dim3(T_SEQ/32, D_MOD/32, N_BH), dim3(32, 8)>>>(p_vcat, p_vtr, p_vti);

    // Attention
    score_mma<<<dim3(16, 16, N_BH), tpb, 61440>>>(p_qcat, p_kcat, p_sc);
    softmax_rows<<<(unsigned)(N_BH * T_SEQ), tpb>>>(p_sc, p_attn);
    // ctx writes o-proj input acat directly (acat2 free after k/v projections)
    ctx_mma<<<dim3(16, 2, 2 * N_BH), tpb, 61440>>>(p_attn, p_vtr, p_vti, p_acat2);

    // Output projection (fp32 out) + fused gate/finalize
    proj_mma<<<proj_grid, tpb, 61440>>>(p_acat2, p_wo, o_br, o_bi, p_or, p_oi);
    convert_mag<<<16384, tpb>>>(p_or, p_oi, p_qcat);   // reuse qcat as magcat
    gate_mma<<<dim3(M_TOT / 128, 2), tpb, 61440>>>(p_qcat, p_wg, gate_b,
                                                   p_or, p_oi, (float*)d_out);
}